// round 1
// baseline (speedup 1.0000x reference)
#include <cuda_runtime.h>
#include <mma.h>

using namespace nvcuda;

#define LDP     264   // row pitch (floats) for 64x256 smem buffers (32B aligned rows, 8-bank shift)
#define SPITCH  72    // score buffer pitch
#define PPITCH  264   // weight panel pitch
#define OUT_HALF 16777216  // 8*64*128*256

// ---------------- folded-weight scratch (static device memory; no allocs) ----------
__device__ float g_Wq[2][256 * 256];   // diag(g_qnorm) @ Wq
__device__ float g_Wkv[2][256 * 256];  // [ diag(g_kvnorm)@Wk | diag(g_kvnorm)@Wv ]
__device__ float g_bq[2][256];         // b_qnorm @ Wq + bq
__device__ float g_bkv[2][256];        // [ b_kvnorm@Wk + bk | b_kvnorm@Wv + bv ]

// ---------------- prep kernel 1: fold LN gamma into weights -----------------------
__global__ void prep_weights(const float* __restrict__ gq0, const float* __restrict__ gkv0,
                             const float* __restrict__ gq1, const float* __restrict__ gkv1,
                             const float* __restrict__ Wq0, const float* __restrict__ Wk0,
                             const float* __restrict__ Wv0,
                             const float* __restrict__ Wq1, const float* __restrict__ Wk1,
                             const float* __restrict__ Wv1) {
    int idx = blockIdx.x * blockDim.x + threadIdx.x;   // 0 .. 262143
    int br   = idx >> 17;
    int rest = idx & 131071;
    int mat  = rest >> 16;
    int e    = rest & 65535;
    int k = e >> 8, j = e & 255;
    const float* gq  = br ? gq1  : gq0;
    const float* gkv = br ? gkv1 : gkv0;
    const float* Wq  = br ? Wq1  : Wq0;
    const float* Wk  = br ? Wk1  : Wk0;
    const float* Wv  = br ? Wv1  : Wv0;
    if (mat == 0) {
        g_Wq[br][e] = gq[k] * Wq[e];
    } else {
        float w = (j < 128) ? Wk[k * 128 + j] : Wv[k * 128 + (j - 128)];
        g_Wkv[br][e] = gkv[k] * w;
    }
}

// ---------------- prep kernel 2: fold LN beta into biases -------------------------
__global__ void prep_bias(const float* __restrict__ bqn0, const float* __restrict__ bkvn0,
                          const float* __restrict__ bqn1, const float* __restrict__ bkvn1,
                          const float* __restrict__ Wq0, const float* __restrict__ Wk0,
                          const float* __restrict__ Wv0, const float* __restrict__ bq0,
                          const float* __restrict__ bk0, const float* __restrict__ bv0,
                          const float* __restrict__ Wq1, const float* __restrict__ Wk1,
                          const float* __restrict__ Wv1, const float* __restrict__ bq1,
                          const float* __restrict__ bk1, const float* __restrict__ bv1) {
    int idx = blockIdx.x * blockDim.x + threadIdx.x;
    if (idx >= 1024) return;
    int br = idx >> 9;
    int t  = idx & 511;
    const float* bqn  = br ? bqn1  : bqn0;
    const float* bkvn = br ? bkvn1 : bkvn0;
    const float* Wq = br ? Wq1 : Wq0;
    const float* Wk = br ? Wk1 : Wk0;
    const float* Wv = br ? Wv1 : Wv0;
    const float* bq = br ? bq1 : bq0;
    const float* bk = br ? bk1 : bk0;
    const float* bv = br ? bv1 : bv0;
    if (t < 256) {
        float acc = bq[t];
        for (int k = 0; k < 256; ++k) acc += bqn[k] * Wq[k * 256 + t];
        g_bq[br][t] = acc;
    } else {
        int tt = t - 256;
        if (tt < 128) {
            float acc = bk[tt];
            for (int k = 0; k < 256; ++k) acc += bkvn[k] * Wk[k * 128 + tt];
            g_bkv[br][tt] = acc;
        } else {
            int vv = tt - 128;
            float acc = bv[vv];
            for (int k = 0; k < 256; ++k) acc += bkvn[k] * Wv[k * 128 + vv];
            g_bkv[br][tt] = acc;
        }
    }
}

// ---------------- main fused kernel helpers ---------------------------------------
template <class F>
__device__ __forceinline__ void to_tf32(F& f) {
#pragma unroll
    for (int i = 0; i < f.num_elements; ++i) f.x[i] = wmma::__float_to_tf32(f.x[i]);
}

// normalized (no-affine) LayerNorm of a [64 x 256] sequence, row stride 32768 floats
__device__ __forceinline__ void ln_rows(float* dst, const float* __restrict__ src, int tid) {
    int warp = tid >> 5, lane = tid & 31;
    for (int r = warp; r < 64; r += 8) {
        const float* rp = src + r * 32768;
        float4 u = *reinterpret_cast<const float4*>(rp + lane * 8);
        float4 w = *reinterpret_cast<const float4*>(rp + lane * 8 + 4);
        float s = u.x + u.y + u.z + u.w + w.x + w.y + w.z + w.w;
        float q = u.x * u.x + u.y * u.y + u.z * u.z + u.w * u.w +
                  w.x * w.x + w.y * w.y + w.z * w.z + w.w * w.w;
#pragma unroll
        for (int o = 16; o; o >>= 1) {
            s += __shfl_xor_sync(0xffffffffu, s, o);
            q += __shfl_xor_sync(0xffffffffu, q, o);
        }
        float mu  = s * (1.0f / 256.0f);
        float var = q * (1.0f / 256.0f) - mu * mu;
        float rs  = rsqrtf(var + 1e-5f);
        float* d = dst + r * LDP + lane * 8;
        d[0] = (u.x - mu) * rs; d[1] = (u.y - mu) * rs;
        d[2] = (u.z - mu) * rs; d[3] = (u.w - mu) * rs;
        d[4] = (w.x - mu) * rs; d[5] = (w.y - mu) * rs;
        d[6] = (w.z - mu) * rs; d[7] = (w.w - mu) * rs;
    }
}

// stage an 8(k) x 256(n) fp32 weight panel into smem (coalesced float4)
__device__ __forceinline__ void stage_panel(float* dst, const float* __restrict__ W,
                                            int k0, int tid) {
    int r = tid >> 5;
    int c = (tid & 31) * 8;
    const float4* s = reinterpret_cast<const float4*>(W + (k0 + r) * 256 + c);
    float4* d = reinterpret_cast<float4*>(dst + r * PPITCH + c);
    d[0] = s[0];
    d[1] = s[1];
}

// C[64x256] = A[64x256] @ W[256x256] + bias ; A,C in smem (pitch LDP), W row-major gmem
__device__ __forceinline__ void gemm64x256(const float* A, const float* __restrict__ W,
                                           const float* __restrict__ bias, float* C,
                                           float* panel, int tid) {
    int warp = tid >> 5;
    int m0 = (warp & 3) * 16;
    int n0 = (warp >> 2) * 128;
    wmma::fragment<wmma::accumulator, 16, 16, 8, float> acc[8];
#pragma unroll
    for (int i = 0; i < 8; ++i) wmma::fill_fragment(acc[i], 0.0f);
    stage_panel(panel, W, 0, tid);
    __syncthreads();
    for (int kt = 0; kt < 32; ++kt) {
        const float* cur = panel + (kt & 1) * (8 * PPITCH);
        if (kt < 31) stage_panel(panel + ((kt + 1) & 1) * (8 * PPITCH), W, (kt + 1) * 8, tid);
        wmma::fragment<wmma::matrix_a, 16, 16, 8, wmma::precision::tf32, wmma::row_major> a;
        wmma::load_matrix_sync(a, A + m0 * LDP + kt * 8, LDP);
        to_tf32(a);
#pragma unroll
        for (int nt = 0; nt < 8; ++nt) {
            wmma::fragment<wmma::matrix_b, 16, 16, 8, wmma::precision::tf32, wmma::row_major> bf;
            wmma::load_matrix_sync(bf, cur + n0 + nt * 16, PPITCH);
            to_tf32(bf);
            wmma::mma_sync(acc[nt], a, bf, acc[nt]);
        }
        __syncthreads();
    }
#pragma unroll
    for (int nt = 0; nt < 8; ++nt)
        wmma::store_matrix_sync(C + m0 * LDP + n0 + nt * 16, acc[nt], LDP, wmma::mem_row_major);
    __syncthreads();
    for (int idx = tid; idx < 64 * 256; idx += 256) {
        int r = idx >> 8, j = idx & 255;
        C[r * LDP + j] += bias[j];
    }
    __syncthreads();
}

// GQA attention: Q[64x256], KV[64x256] (K cols 0..127, V cols 128..255) -> AO[64x256]
__device__ __forceinline__ void attention(const float* Q, const float* KV, float* AO,
                                          float* sc, int tid) {
    int warp = tid >> 5;
    const float scale = 0.17677669529663687f;  // 1/sqrt(32)
    for (int h = 0; h < 8; ++h) {
        int qo = h * 32;
        int ko = (h >> 1) * 32;
        int vo = 128 + (h >> 1) * 32;
        // ---- scores = Q_h @ K_h^T * scale  (16 tiles of 16x16, 2 per warp)
#pragma unroll
        for (int tt = 0; tt < 2; ++tt) {
            int tile = warp * 2 + tt;
            int m0 = (tile >> 2) * 16, n0 = (tile & 3) * 16;
            wmma::fragment<wmma::accumulator, 16, 16, 8, float> acc;
            wmma::fill_fragment(acc, 0.0f);
#pragma unroll
            for (int k = 0; k < 4; ++k) {
                wmma::fragment<wmma::matrix_a, 16, 16, 8, wmma::precision::tf32, wmma::row_major> a;
                wmma::load_matrix_sync(a, Q + m0 * LDP + qo + k * 8, LDP);
                to_tf32(a);
                wmma::fragment<wmma::matrix_b, 16, 16, 8, wmma::precision::tf32, wmma::col_major> bf;
                wmma::load_matrix_sync(bf, KV + n0 * LDP + ko + k * 8, LDP);
                to_tf32(bf);
                wmma::mma_sync(acc, a, bf, acc);
            }
#pragma unroll
            for (int i = 0; i < acc.num_elements; ++i) acc.x[i] *= scale;
            wmma::store_matrix_sync(sc + m0 * SPITCH + n0, acc, SPITCH, wmma::mem_row_major);
        }
        __syncthreads();
        // ---- row softmax: 4 lanes per row, 16 cols each
        {
            float* srow = sc + (tid >> 2) * SPITCH + (tid & 3) * 16;
            float4* sr4 = reinterpret_cast<float4*>(srow);
            float v[16];
#pragma unroll
            for (int i = 0; i < 4; ++i) {
                float4 t = sr4[i];
                v[4 * i] = t.x; v[4 * i + 1] = t.y; v[4 * i + 2] = t.z; v[4 * i + 3] = t.w;
            }
            float mx = v[0];
#pragma unroll
            for (int i = 1; i < 16; ++i) mx = fmaxf(mx, v[i]);
            mx = fmaxf(mx, __shfl_xor_sync(0xffffffffu, mx, 1));
            mx = fmaxf(mx, __shfl_xor_sync(0xffffffffu, mx, 2));
            float sum = 0.0f;
#pragma unroll
            for (int i = 0; i < 16; ++i) { v[i] = __expf(v[i] - mx); sum += v[i]; }
            sum += __shfl_xor_sync(0xffffffffu, sum, 1);
            sum += __shfl_xor_sync(0xffffffffu, sum, 2);
            float inv = 1.0f / sum;
#pragma unroll
            for (int i = 0; i < 4; ++i) {
                float4 t;
                t.x = v[4 * i] * inv;     t.y = v[4 * i + 1] * inv;
                t.z = v[4 * i + 2] * inv; t.w = v[4 * i + 3] * inv;
                sr4[i] = t;
            }
        }
        __syncthreads();
        // ---- AO_h = P @ V_h  (8 tiles of 16x16, 1 per warp)
        {
            int m0 = (warp >> 1) * 16, n0 = (warp & 1) * 16;
            wmma::fragment<wmma::accumulator, 16, 16, 8, float> acc;
            wmma::fill_fragment(acc, 0.0f);
#pragma unroll
            for (int k = 0; k < 8; ++k) {
                wmma::fragment<wmma::matrix_a, 16, 16, 8, wmma::precision::tf32, wmma::row_major> a;
                wmma::load_matrix_sync(a, sc + m0 * SPITCH + k * 8, SPITCH);
                to_tf32(a);
                wmma::fragment<wmma::matrix_b, 16, 16, 8, wmma::precision::tf32, wmma::row_major> bf;
                wmma::load_matrix_sync(bf, KV + (k * 8) * LDP + vo + n0, LDP);
                to_tf32(bf);
                wmma::mma_sync(acc, a, bf, acc);
            }
            wmma::store_matrix_sync(AO + m0 * LDP + qo + n0, acc, LDP, wmma::mem_row_major);
        }
        __syncthreads();
    }
}

// ---------------- main fused kernel: 1 CTA per (sequence, branch) -----------------
__global__ void __launch_bounds__(256, 1)
fusion_kernel(const float* __restrict__ xspec, const float* __restrict__ xspat,
              const float* __restrict__ Wo0, const float* __restrict__ bo0,
              const float* __restrict__ Wo1, const float* __restrict__ bo1,
              const float* __restrict__ gate0, const float* __restrict__ gate1,
              float* __restrict__ out) {
    extern __shared__ float sm[];
    float* bufA  = sm;                 // x_hat  -> attn out
    float* bufQ  = sm + 64 * LDP;      // Q      -> O-proj result
    float* bufKV = sm + 2 * 64 * LDP;  // K | V
    float* aux   = sm + 3 * 64 * LDP;  // weight panels / score buffer (aliased)

    int tid = threadIdx.x;
    int br = blockIdx.x & 1;
    int bc = blockIdx.x >> 1;
    int b = bc >> 7, c = bc & 127;
    int base = (b * 8192 + c) * 256;   // [B,S,C,D] token (b, s=0, c)

    const float* xq  = br ? xspat : xspec;
    const float* xkv = br ? xspec : xspat;
    const float* Wq  = g_Wq[br];
    const float* Wkv = g_Wkv[br];
    const float* bq  = g_bq[br];
    const float* bkv = g_bkv[br];
    const float* Wo  = br ? Wo1 : Wo0;
    const float* bo  = br ? bo1 : bo0;
    float gv = br ? gate1[0] : gate0[0];
    float sg = 1.0f / (1.0f + __expf(-gv));
    float* outb = out + (br ? OUT_HALF : 0);

    // 1) KV path: x_hat(kv) -> [K|V]
    ln_rows(bufA, xkv + base, tid);
    __syncthreads();
    gemm64x256(bufA, Wkv, bkv, bufKV, aux, tid);

    // 2) Q path: x_hat(q) -> Q
    ln_rows(bufA, xq + base, tid);
    __syncthreads();
    gemm64x256(bufA, Wq, bq, bufQ, aux, tid);

    // 3) attention (writes bufA = attn output, all 256 cols covered by 8 heads)
    attention(bufQ, bufKV, bufA, aux, tid);

    // 4) output projection: delta = AO @ Wo + bo  (into bufQ)
    gemm64x256(bufA, Wo, bo, bufQ, aux, tid);

    // 5) epilogue: out = x + sigmoid(gate) * delta   (coalesced, [B,S,C,D] layout)
    for (int r = 0; r < 64; ++r) {
        int off = base + r * 32768 + tid;
        outb[off] = xq[off] + sg * bufQ[r * LDP + tid];
    }
}

// ---------------- host launcher -----------------------------------------------------
extern "C" void kernel_launch(void* const* d_in, const int* in_sizes, int n_in,
                              void* d_out, int out_size) {
    const float* xspec = (const float*)d_in[0];
    const float* xspat = (const float*)d_in[1];
    const float* lsqg  = (const float*)d_in[2];
    const float* lsqb  = (const float*)d_in[3];
    const float* lskvg = (const float*)d_in[4];
    const float* lskvb = (const float*)d_in[5];
    const float* ltqg  = (const float*)d_in[6];
    const float* ltqb  = (const float*)d_in[7];
    const float* ltkvg = (const float*)d_in[8];
    const float* ltkvb = (const float*)d_in[9];
    const float* Wq0 = (const float*)d_in[10]; const float* bq0 = (const float*)d_in[11];
    const float* Wk0 = (const float*)d_in[12]; const float* bk0 = (const float*)d_in[13];
    const float* Wv0 = (const float*)d_in[14]; const float* bv0 = (const float*)d_in[15];
    const float* Wo0 = (const float*)d_in[16]; const float* bo0 = (const float*)d_in[17];
    const float* Wq1 = (const float*)d_in[18]; const float* bq1 = (const float*)d_in[19];
    const float* Wk1 = (const float*)d_in[20]; const float* bk1 = (const float*)d_in[21];
    const float* Wv1 = (const float*)d_in[22]; const float* bv1 = (const float*)d_in[23];
    const float* Wo1 = (const float*)d_in[24]; const float* bo1 = (const float*)d_in[25];
    const float* g0  = (const float*)d_in[26];
    const float* g1  = (const float*)d_in[27];
    float* out = (float*)d_out;

    // branch 0 (s2t): q-norm = spec_q, kv-norm = spat_kv
    // branch 1 (t2s): q-norm = spat_q, kv-norm = spec_kv
    prep_weights<<<1024, 256>>>(lsqg, ltkvg, ltqg, lskvg,
                                Wq0, Wk0, Wv0, Wq1, Wk1, Wv1);
    prep_bias<<<4, 256>>>(lsqb, ltkvb, ltqb, lskvb,
                          Wq0, Wk0, Wv0, bq0, bk0, bv0,
                          Wq1, Wk1, Wv1, bq1, bk1, bv1);

    const int SMEM = (3 * 64 * LDP + 64 * SPITCH) * 4;  // 221184 bytes
    cudaFuncSetAttribute(fusion_kernel, cudaFuncAttributeMaxDynamicSharedMemorySize, SMEM);
    fusion_kernel<<<2048, 256, SMEM>>>(xspec, xspat, Wo0, bo0, Wo1, bo1, g0, g1, out);
}

// round 2
// speedup vs baseline: 1.1942x; 1.1942x over previous
#include <cuda_runtime.h>
#include <mma.h>

using namespace nvcuda;

#define LDP     264   // row pitch (floats) for 64x256 smem buffers
#define SPITCH  72    // score buffer pitch
#define PPITCH  264   // weight panel pitch
#define OUT_HALF 16777216  // 8*64*128*256

// ---------------- folded-weight scratch (static device memory; no allocs) ----------
__device__ float g_Wq[2][256 * 256];   // diag(g_qnorm) @ Wq
__device__ float g_Wkv[2][256 * 256];  // [ diag(g_kvnorm)@Wk | diag(g_kvnorm)@Wv ]
__device__ float g_bq[2][256];         // b_qnorm @ Wq + bq
__device__ float g_bkv[2][256];        // [ b_kvnorm@Wk + bk | b_kvnorm@Wv + bv ]

// ---------------- prep kernel 1: fold LN gamma into weights -----------------------
__global__ void prep_weights(const float* __restrict__ gq0, const float* __restrict__ gkv0,
                             const float* __restrict__ gq1, const float* __restrict__ gkv1,
                             const float* __restrict__ Wq0, const float* __restrict__ Wk0,
                             const float* __restrict__ Wv0,
                             const float* __restrict__ Wq1, const float* __restrict__ Wk1,
                             const float* __restrict__ Wv1) {
    int idx = blockIdx.x * blockDim.x + threadIdx.x;   // 0 .. 262143
    int br   = idx >> 17;
    int rest = idx & 131071;
    int mat  = rest >> 16;
    int e    = rest & 65535;
    int k = e >> 8, j = e & 255;
    const float* gq  = br ? gq1  : gq0;
    const float* gkv = br ? gkv1 : gkv0;
    const float* Wq  = br ? Wq1  : Wq0;
    const float* Wk  = br ? Wk1  : Wk0;
    const float* Wv  = br ? Wv1  : Wv0;
    if (mat == 0) {
        g_Wq[br][e] = gq[k] * Wq[e];
    } else {
        float w = (j < 128) ? Wk[k * 128 + j] : Wv[k * 128 + (j - 128)];
        g_Wkv[br][e] = gkv[k] * w;
    }
}

// ---------------- prep kernel 2: fold LN beta into biases -------------------------
__global__ void prep_bias(const float* __restrict__ bqn0, const float* __restrict__ bkvn0,
                          const float* __restrict__ bqn1, const float* __restrict__ bkvn1,
                          const float* __restrict__ Wq0, const float* __restrict__ Wk0,
                          const float* __restrict__ Wv0, const float* __restrict__ bq0,
                          const float* __restrict__ bk0, const float* __restrict__ bv0,
                          const float* __restrict__ Wq1, const float* __restrict__ Wk1,
                          const float* __restrict__ Wv1, const float* __restrict__ bq1,
                          const float* __restrict__ bk1, const float* __restrict__ bv1) {
    int idx = blockIdx.x * blockDim.x + threadIdx.x;
    if (idx >= 1024) return;
    int br = idx >> 9;
    int t  = idx & 511;
    const float* bqn  = br ? bqn1  : bqn0;
    const float* bkvn = br ? bkvn1 : bkvn0;
    const float* Wq = br ? Wq1 : Wq0;
    const float* Wk = br ? Wk1 : Wk0;
    const float* Wv = br ? Wv1 : Wv0;
    const float* bq = br ? bq1 : bq0;
    const float* bk = br ? bk1 : bk0;
    const float* bv = br ? bv1 : bv0;
    if (t < 256) {
        float acc = bq[t];
        for (int k = 0; k < 256; ++k) acc += bqn[k] * Wq[k * 256 + t];
        g_bq[br][t] = acc;
    } else {
        int tt = t - 256;
        if (tt < 128) {
            float acc = bk[tt];
            for (int k = 0; k < 256; ++k) acc += bkvn[k] * Wk[k * 128 + tt];
            g_bkv[br][tt] = acc;
        } else {
            int vv = tt - 128;
            float acc = bv[vv];
            for (int k = 0; k < 256; ++k) acc += bkvn[k] * Wv[k * 128 + vv];
            g_bkv[br][tt] = acc;
        }
    }
}

// ---------------- tf32 rounding helpers --------------------------------------------
__device__ __forceinline__ float r32(float x) { return wmma::__float_to_tf32(x); }
__device__ __forceinline__ float4 r32x4(float4 v) {
    v.x = r32(v.x); v.y = r32(v.y); v.z = r32(v.z); v.w = r32(v.w);
    return v;
}

// normalized (no-affine) LayerNorm of a [64 x 256] sequence, row stride 32768 floats
// output rounded to tf32. 16 warps, 4 rows each.
__device__ __forceinline__ void ln_rows(float* dst, const float* __restrict__ src, int tid) {
    int warp = tid >> 5, lane = tid & 31;
    for (int r = warp; r < 64; r += 16) {
        const float* rp = src + r * 32768;
        float4 u = *reinterpret_cast<const float4*>(rp + lane * 8);
        float4 w = *reinterpret_cast<const float4*>(rp + lane * 8 + 4);
        float s = u.x + u.y + u.z + u.w + w.x + w.y + w.z + w.w;
        float q = u.x * u.x + u.y * u.y + u.z * u.z + u.w * u.w +
                  w.x * w.x + w.y * w.y + w.z * w.z + w.w * w.w;
#pragma unroll
        for (int o = 16; o; o >>= 1) {
            s += __shfl_xor_sync(0xffffffffu, s, o);
            q += __shfl_xor_sync(0xffffffffu, q, o);
        }
        float mu  = s * (1.0f / 256.0f);
        float var = q * (1.0f / 256.0f) - mu * mu;
        float rs  = rsqrtf(var + 1e-5f);
        float4 a, b;
        a.x = (u.x - mu) * rs; a.y = (u.y - mu) * rs;
        a.z = (u.z - mu) * rs; a.w = (u.w - mu) * rs;
        b.x = (w.x - mu) * rs; b.y = (w.y - mu) * rs;
        b.z = (w.z - mu) * rs; b.w = (w.w - mu) * rs;
        float4* d = reinterpret_cast<float4*>(dst + r * LDP + lane * 8);
        d[0] = r32x4(a);
        d[1] = r32x4(b);
    }
}

// C[64x256] = round_tf32((A[64x256] @ W[256x256] + bias) * scale)
// A,C in smem (pitch LDP, A already tf32-rounded), W row-major gmem. 512 threads.
__device__ __forceinline__ void gemm64x256(const float* A, const float* __restrict__ W,
                                           const float* __restrict__ bias, float* C,
                                           float* panel, int tid, float scale) {
    int warp = tid >> 5;                 // 0..15
    int m0 = (warp & 1) * 32;            // warp covers m-tiles {m0, m0+16}
    int n0 = (warp >> 1) * 32;           // and n-tiles {n0, n0+16}
    int pr = tid >> 6;                   // panel stage row 0..7
    int pc = (tid & 63) * 4;             // panel stage col

    wmma::fragment<wmma::accumulator, 16, 16, 8, float> acc[2][2];
#pragma unroll
    for (int i = 0; i < 2; ++i)
#pragma unroll
        for (int j = 0; j < 2; ++j) wmma::fill_fragment(acc[i][j], 0.0f);

    // stage panel 0
    {
        float4 v = *reinterpret_cast<const float4*>(W + pr * 256 + pc);
        *reinterpret_cast<float4*>(panel + pr * PPITCH + pc) = r32x4(v);
    }
    __syncthreads();

    for (int kt = 0; kt < 32; ++kt) {
        float4 nxt;
        if (kt < 31)
            nxt = *reinterpret_cast<const float4*>(W + ((kt + 1) * 8 + pr) * 256 + pc);

        const float* cur = panel + (kt & 1) * (8 * PPITCH);
        wmma::fragment<wmma::matrix_a, 16, 16, 8, wmma::precision::tf32, wmma::row_major> a[2];
        wmma::load_matrix_sync(a[0], A + m0 * LDP + kt * 8, LDP);
        wmma::load_matrix_sync(a[1], A + (m0 + 16) * LDP + kt * 8, LDP);
        wmma::fragment<wmma::matrix_b, 16, 16, 8, wmma::precision::tf32, wmma::row_major> b[2];
        wmma::load_matrix_sync(b[0], cur + n0, PPITCH);
        wmma::load_matrix_sync(b[1], cur + n0 + 16, PPITCH);
#pragma unroll
        for (int i = 0; i < 2; ++i)
#pragma unroll
            for (int j = 0; j < 2; ++j) wmma::mma_sync(acc[i][j], a[i], b[j], acc[i][j]);

        if (kt < 31) {
            float* nb = panel + ((kt + 1) & 1) * (8 * PPITCH);
            *reinterpret_cast<float4*>(nb + pr * PPITCH + pc) = r32x4(nxt);
        }
        __syncthreads();
    }
#pragma unroll
    for (int i = 0; i < 2; ++i)
#pragma unroll
        for (int j = 0; j < 2; ++j)
            wmma::store_matrix_sync(C + (m0 + 16 * i) * LDP + n0 + 16 * j, acc[i][j],
                                    LDP, wmma::mem_row_major);
    __syncthreads();
    // bias + scale + tf32 rounding, vectorized
    for (int idx = tid; idx < 4096; idx += 512) {
        int r = idx >> 6, c = (idx & 63) * 4;
        float4 v = *reinterpret_cast<float4*>(C + r * LDP + c);
        v.x = r32((v.x + bias[c + 0]) * scale);
        v.y = r32((v.y + bias[c + 1]) * scale);
        v.z = r32((v.z + bias[c + 2]) * scale);
        v.w = r32((v.w + bias[c + 3]) * scale);
        *reinterpret_cast<float4*>(C + r * LDP + c) = v;
    }
    __syncthreads();
}

// GQA attention: Q[64x256] (pre-scaled), KV[64x256] (K cols 0..127, V cols 128..255)
// -> AO[64x256]. 512 threads.
__device__ __forceinline__ void attention(const float* Q, const float* KV, float* AO,
                                          float* sc, int tid) {
    int warp = tid >> 5;
    for (int h = 0; h < 8; ++h) {
        int qo = h * 32;
        int ko = (h >> 1) * 32;
        int vo = 128 + (h >> 1) * 32;
        // ---- scores = Q_h @ K_h^T  (16 tiles of 16x16, 1 per warp)
        {
            int m0 = (warp & 3) * 16, n0 = (warp >> 2) * 16;
            wmma::fragment<wmma::accumulator, 16, 16, 8, float> acc;
            wmma::fill_fragment(acc, 0.0f);
#pragma unroll
            for (int k = 0; k < 4; ++k) {
                wmma::fragment<wmma::matrix_a, 16, 16, 8, wmma::precision::tf32, wmma::row_major> a;
                wmma::load_matrix_sync(a, Q + m0 * LDP + qo + k * 8, LDP);
                wmma::fragment<wmma::matrix_b, 16, 16, 8, wmma::precision::tf32, wmma::col_major> bf;
                wmma::load_matrix_sync(bf, KV + n0 * LDP + ko + k * 8, LDP);
                wmma::mma_sync(acc, a, bf, acc);
            }
            wmma::store_matrix_sync(sc + m0 * SPITCH + n0, acc, SPITCH, wmma::mem_row_major);
        }
        __syncthreads();
        // ---- row softmax: 8 lanes per row, 8 cols each
        {
            float* srow = sc + (tid >> 3) * SPITCH + (tid & 7) * 8;
            float4* sr4 = reinterpret_cast<float4*>(srow);
            float v[8];
            float4 t0 = sr4[0], t1 = sr4[1];
            v[0] = t0.x; v[1] = t0.y; v[2] = t0.z; v[3] = t0.w;
            v[4] = t1.x; v[5] = t1.y; v[6] = t1.z; v[7] = t1.w;
            float mx = v[0];
#pragma unroll
            for (int i = 1; i < 8; ++i) mx = fmaxf(mx, v[i]);
            mx = fmaxf(mx, __shfl_xor_sync(0xffffffffu, mx, 1));
            mx = fmaxf(mx, __shfl_xor_sync(0xffffffffu, mx, 2));
            mx = fmaxf(mx, __shfl_xor_sync(0xffffffffu, mx, 4));
            float sum = 0.0f;
#pragma unroll
            for (int i = 0; i < 8; ++i) { v[i] = __expf(v[i] - mx); sum += v[i]; }
            sum += __shfl_xor_sync(0xffffffffu, sum, 1);
            sum += __shfl_xor_sync(0xffffffffu, sum, 2);
            sum += __shfl_xor_sync(0xffffffffu, sum, 4);
            float inv = 1.0f / sum;
            t0.x = r32(v[0] * inv); t0.y = r32(v[1] * inv);
            t0.z = r32(v[2] * inv); t0.w = r32(v[3] * inv);
            t1.x = r32(v[4] * inv); t1.y = r32(v[5] * inv);
            t1.z = r32(v[6] * inv); t1.w = r32(v[7] * inv);
            sr4[0] = t0; sr4[1] = t1;
        }
        __syncthreads();
        // ---- AO_h = P @ V_h  (8 tiles of 16x16, warps 0..7)
        if (warp < 8) {
            int m0 = (warp >> 1) * 16, n0 = (warp & 1) * 16;
            wmma::fragment<wmma::accumulator, 16, 16, 8, float> acc;
            wmma::fill_fragment(acc, 0.0f);
#pragma unroll
            for (int k = 0; k < 8; ++k) {
                wmma::fragment<wmma::matrix_a, 16, 16, 8, wmma::precision::tf32, wmma::row_major> a;
                wmma::load_matrix_sync(a, sc + m0 * SPITCH + k * 8, SPITCH);
                wmma::fragment<wmma::matrix_b, 16, 16, 8, wmma::precision::tf32, wmma::row_major> bf;
                wmma::load_matrix_sync(bf, KV + (k * 8) * LDP + vo + n0, LDP);
                wmma::mma_sync(acc, a, bf, acc);
            }
            wmma::store_matrix_sync(AO + m0 * LDP + qo + n0, acc, LDP, wmma::mem_row_major);
        }
        __syncthreads();
    }
}

// ---------------- main fused kernel: 1 CTA per (sequence, branch) -----------------
__global__ void __launch_bounds__(512, 1)
fusion_kernel(const float* __restrict__ xspec, const float* __restrict__ xspat,
              const float* __restrict__ Wo0, const float* __restrict__ bo0,
              const float* __restrict__ Wo1, const float* __restrict__ bo1,
              const float* __restrict__ gate0, const float* __restrict__ gate1,
              float* __restrict__ out) {
    extern __shared__ float sm[];
    float* bufA  = sm;                 // x_hat  -> attn out
    float* bufQ  = sm + 64 * LDP;      // Q      -> O-proj result
    float* bufKV = sm + 2 * 64 * LDP;  // K | V
    float* aux   = sm + 3 * 64 * LDP;  // weight panels / score buffer (aliased)

    int tid = threadIdx.x;
    int br = blockIdx.x & 1;
    int bc = blockIdx.x >> 1;
    int b = bc >> 7, c = bc & 127;
    int base = (b * 8192 + c) * 256;   // [B,S,C,D] token (b, s=0, c)

    const float* xq  = br ? xspat : xspec;
    const float* xkv = br ? xspec : xspat;
    const float* Wq  = g_Wq[br];
    const float* Wkv = g_Wkv[br];
    const float* bq  = g_bq[br];
    const float* bkv = g_bkv[br];
    const float* Wo  = br ? Wo1 : Wo0;
    const float* bo  = br ? bo1 : bo0;
    float gv = br ? gate1[0] : gate0[0];
    float sg = 1.0f / (1.0f + __expf(-gv));
    float* outb = out + (br ? OUT_HALF : 0);

    // 1) KV path: x_hat(kv) -> [K|V]
    ln_rows(bufA, xkv + base, tid);
    __syncthreads();
    gemm64x256(bufA, Wkv, bkv, bufKV, aux, tid, 1.0f);

    // 2) Q path: x_hat(q) -> Q (pre-scaled by 1/sqrt(32))
    ln_rows(bufA, xq + base, tid);
    __syncthreads();
    gemm64x256(bufA, Wq, bq, bufQ, aux, tid, 0.17677669529663687f);

    // 3) attention (writes bufA = attn output)
    attention(bufQ, bufKV, bufA, aux, tid);

    // 4) output projection: delta = AO @ Wo + bo  (into bufQ)
    gemm64x256(bufA, Wo, bo, bufQ, aux, tid, 1.0f);

    // 5) epilogue: out = x + sigmoid(gate) * delta (coalesced, float4)
    for (int i = tid; i < 4096; i += 512) {
        int r = i >> 6, cc = (i & 63) * 4;
        int off = base + r * 32768 + cc;
        float4 x = *reinterpret_cast<const float4*>(xq + off);
        float4 d = *reinterpret_cast<const float4*>(bufQ + r * LDP + cc);
        x.x += sg * d.x; x.y += sg * d.y; x.z += sg * d.z; x.w += sg * d.w;
        *reinterpret_cast<float4*>(outb + off) = x;
    }
}

// ---------------- host launcher -----------------------------------------------------
extern "C" void kernel_launch(void* const* d_in, const int* in_sizes, int n_in,
                              void* d_out, int out_size) {
    const float* xspec = (const float*)d_in[0];
    const float* xspat = (const float*)d_in[1];
    const float* lsqg  = (const float*)d_in[2];
    const float* lsqb  = (const float*)d_in[3];
    const float* lskvg = (const float*)d_in[4];
    const float* lskvb = (const float*)d_in[5];
    const float* ltqg  = (const float*)d_in[6];
    const float* ltqb  = (const float*)d_in[7];
    const float* ltkvg = (const float*)d_in[8];
    const float* ltkvb = (const float*)d_in[9];
    const float* Wq0 = (const float*)d_in[10]; const float* bq0 = (const float*)d_in[11];
    const float* Wk0 = (const float*)d_in[12]; const float* bk0 = (const float*)d_in[13];
    const float* Wv0 = (const float*)d_in[14]; const float* bv0 = (const float*)d_in[15];
    const float* Wo0 = (const float*)d_in[16]; const float* bo0 = (const float*)d_in[17];
    const float* Wq1 = (const float*)d_in[18]; const float* bq1 = (const float*)d_in[19];
    const float* Wk1 = (const float*)d_in[20]; const float* bk1 = (const float*)d_in[21];
    const float* Wv1 = (const float*)d_in[22]; const float* bv1 = (const float*)d_in[23];
    const float* Wo1 = (const float*)d_in[24]; const float* bo1 = (const float*)d_in[25];
    const float* g0  = (const float*)d_in[26];
    const float* g1  = (const float*)d_in[27];
    float* out = (float*)d_out;

    // branch 0 (s2t): q-norm = spec_q, kv-norm = spat_kv
    // branch 1 (t2s): q-norm = spat_q, kv-norm = spec_kv
    prep_weights<<<1024, 256>>>(lsqg, ltkvg, ltqg, lskvg,
                                Wq0, Wk0, Wv0, Wq1, Wk1, Wv1);
    prep_bias<<<4, 256>>>(lsqb, ltkvb, ltqb, lskvb,
                          Wq0, Wk0, Wv0, bq0, bk0, bv0,
                          Wq1, Wk1, Wv1, bq1, bk1, bv1);

    const int SMEM = (3 * 64 * LDP + 64 * SPITCH) * 4;  // 221184 bytes
    cudaFuncSetAttribute(fusion_kernel, cudaFuncAttributeMaxDynamicSharedMemorySize, SMEM);
    fusion_kernel<<<2048, 512, SMEM>>>(xspec, xspat, Wo0, bo0, Wo1, bo1, g0, g1, out);
}

// round 3
// speedup vs baseline: 1.1945x; 1.0003x over previous
#include <cuda_runtime.h>
#include <mma.h>

using namespace nvcuda;

#define LDP     264   // row pitch (floats) for 64x256 smem buffers
#define SPITCH  72    // score buffer pitch
#define PPITCH  264   // weight panel pitch
#define OUT_HALF 16777216  // 8*64*128*256

// ---------------- folded-weight scratch (static device memory; no allocs) ----------
__device__ float g_Wq[2][256 * 256];   // diag(g_qnorm) @ Wq
__device__ float g_Wkv[2][256 * 256];  // [ diag(g_kvnorm)@Wk | diag(g_kvnorm)@Wv ]
__device__ float g_bq[2][256];         // b_qnorm @ Wq + bq
__device__ float g_bkv[2][256];        // [ b_kvnorm@Wk + bk | b_kvnorm@Wv + bv ]

// ---------------- prep kernel 1: fold LN gamma into weights -----------------------
__global__ void prep_weights(const float* __restrict__ gq0, const float* __restrict__ gkv0,
                             const float* __restrict__ gq1, const float* __restrict__ gkv1,
                             const float* __restrict__ Wq0, const float* __restrict__ Wk0,
                             const float* __restrict__ Wv0,
                             const float* __restrict__ Wq1, const float* __restrict__ Wk1,
                             const float* __restrict__ Wv1) {
    int idx = blockIdx.x * blockDim.x + threadIdx.x;   // 0 .. 262143
    int br   = idx >> 17;
    int rest = idx & 131071;
    int mat  = rest >> 16;
    int e    = rest & 65535;
    int k = e >> 8, j = e & 255;
    const float* gq  = br ? gq1  : gq0;
    const float* gkv = br ? gkv1 : gkv0;
    const float* Wq  = br ? Wq1  : Wq0;
    const float* Wk  = br ? Wk1  : Wk0;
    const float* Wv  = br ? Wv1  : Wv0;
    if (mat == 0) {
        g_Wq[br][e] = gq[k] * Wq[e];
    } else {
        float w = (j < 128) ? Wk[k * 128 + j] : Wv[k * 128 + (j - 128)];
        g_Wkv[br][e] = gkv[k] * w;
    }
}

// ---------------- prep kernel 2: fold LN beta into biases -------------------------
__global__ void prep_bias(const float* __restrict__ bqn0, const float* __restrict__ bkvn0,
                          const float* __restrict__ bqn1, const float* __restrict__ bkvn1,
                          const float* __restrict__ Wq0, const float* __restrict__ Wk0,
                          const float* __restrict__ Wv0, const float* __restrict__ bq0,
                          const float* __restrict__ bk0, const float* __restrict__ bv0,
                          const float* __restrict__ Wq1, const float* __restrict__ Wk1,
                          const float* __restrict__ Wv1, const float* __restrict__ bq1,
                          const float* __restrict__ bk1, const float* __restrict__ bv1) {
    int idx = blockIdx.x * blockDim.x + threadIdx.x;
    if (idx >= 1024) return;
    int br = idx >> 9;
    int t  = idx & 511;
    const float* bqn  = br ? bqn1  : bqn0;
    const float* bkvn = br ? bkvn1 : bkvn0;
    const float* Wq = br ? Wq1 : Wq0;
    const float* Wk = br ? Wk1 : Wk0;
    const float* Wv = br ? Wv1 : Wv0;
    const float* bq = br ? bq1 : bq0;
    const float* bk = br ? bk1 : bk0;
    const float* bv = br ? bv1 : bv0;
    if (t < 256) {
        float acc = bq[t];
        for (int k = 0; k < 256; ++k) acc += bqn[k] * Wq[k * 256 + t];
        g_bq[br][t] = acc;
    } else {
        int tt = t - 256;
        if (tt < 128) {
            float acc = bk[tt];
            for (int k = 0; k < 256; ++k) acc += bkvn[k] * Wk[k * 128 + tt];
            g_bkv[br][tt] = acc;
        } else {
            int vv = tt - 128;
            float acc = bv[vv];
            for (int k = 0; k < 256; ++k) acc += bkvn[k] * Wv[k * 128 + vv];
            g_bkv[br][tt] = acc;
        }
    }
}

// ---------------- tf32 rounding helpers --------------------------------------------
__device__ __forceinline__ float r32(float x) { return wmma::__float_to_tf32(x); }
__device__ __forceinline__ float4 r32x4(float4 v) {
    v.x = r32(v.x); v.y = r32(v.y); v.z = r32(v.z); v.w = r32(v.w);
    return v;
}

// normalized (no-affine) LayerNorm of a [64 x 256] sequence, row stride 32768 floats
// output rounded to tf32. 16 warps, 4 rows each.
__device__ __forceinline__ void ln_rows(float* dst, const float* __restrict__ src, int tid) {
    int warp = tid >> 5, lane = tid & 31;
    for (int r = warp; r < 64; r += 16) {
        const float* rp = src + r * 32768;
        float4 u = *reinterpret_cast<const float4*>(rp + lane * 8);
        float4 w = *reinterpret_cast<const float4*>(rp + lane * 8 + 4);
        float s = u.x + u.y + u.z + u.w + w.x + w.y + w.z + w.w;
        float q = u.x * u.x + u.y * u.y + u.z * u.z + u.w * u.w +
                  w.x * w.x + w.y * w.y + w.z * w.z + w.w * w.w;
#pragma unroll
        for (int o = 16; o; o >>= 1) {
            s += __shfl_xor_sync(0xffffffffu, s, o);
            q += __shfl_xor_sync(0xffffffffu, q, o);
        }
        float mu  = s * (1.0f / 256.0f);
        float var = q * (1.0f / 256.0f) - mu * mu;
        float rs  = rsqrtf(var + 1e-5f);
        float4 a, b;
        a.x = (u.x - mu) * rs; a.y = (u.y - mu) * rs;
        a.z = (u.z - mu) * rs; a.w = (u.w - mu) * rs;
        b.x = (w.x - mu) * rs; b.y = (w.y - mu) * rs;
        b.z = (w.z - mu) * rs; b.w = (w.w - mu) * rs;
        float4* d = reinterpret_cast<float4*>(dst + r * LDP + lane * 8);
        d[0] = r32x4(a);
        d[1] = r32x4(b);
    }
}

// C[64x256] = round_tf32((A[64x256] @ W[256x256] + bias) * scale)
// A,C in smem (pitch LDP, A already tf32-rounded), W row-major gmem. 512 threads.
__device__ __forceinline__ void gemm64x256(const float* A, const float* __restrict__ W,
                                           const float* __restrict__ bias, float* C,
                                           float* panel, int tid, float scale) {
    int warp = tid >> 5;                 // 0..15
    int m0 = (warp & 1) * 32;            // warp covers m-tiles {m0, m0+16}
    int n0 = (warp >> 1) * 32;           // and n-tiles {n0, n0+16}
    int pr = tid >> 6;                   // panel stage row 0..7
    int pc = (tid & 63) * 4;             // panel stage col

    wmma::fragment<wmma::accumulator, 16, 16, 8, float> acc[2][2];
#pragma unroll
    for (int i = 0; i < 2; ++i)
#pragma unroll
        for (int j = 0; j < 2; ++j) wmma::fill_fragment(acc[i][j], 0.0f);

    // stage panel 0
    {
        float4 v = *reinterpret_cast<const float4*>(W + pr * 256 + pc);
        *reinterpret_cast<float4*>(panel + pr * PPITCH + pc) = r32x4(v);
    }
    __syncthreads();

    for (int kt = 0; kt < 32; ++kt) {
        float4 nxt;
        if (kt < 31)
            nxt = *reinterpret_cast<const float4*>(W + ((kt + 1) * 8 + pr) * 256 + pc);

        const float* cur = panel + (kt & 1) * (8 * PPITCH);
        wmma::fragment<wmma::matrix_a, 16, 16, 8, wmma::precision::tf32, wmma::row_major> a[2];
        wmma::load_matrix_sync(a[0], A + m0 * LDP + kt * 8, LDP);
        wmma::load_matrix_sync(a[1], A + (m0 + 16) * LDP + kt * 8, LDP);
        wmma::fragment<wmma::matrix_b, 16, 16, 8, wmma::precision::tf32, wmma::row_major> b[2];
        wmma::load_matrix_sync(b[0], cur + n0, PPITCH);
        wmma::load_matrix_sync(b[1], cur + n0 + 16, PPITCH);
#pragma unroll
        for (int i = 0; i < 2; ++i)
#pragma unroll
            for (int j = 0; j < 2; ++j) wmma::mma_sync(acc[i][j], a[i], b[j], acc[i][j]);

        if (kt < 31) {
            float* nb = panel + ((kt + 1) & 1) * (8 * PPITCH);
            *reinterpret_cast<float4*>(nb + pr * PPITCH + pc) = r32x4(nxt);
        }
        __syncthreads();
    }
#pragma unroll
    for (int i = 0; i < 2; ++i)
#pragma unroll
        for (int j = 0; j < 2; ++j)
            wmma::store_matrix_sync(C + (m0 + 16 * i) * LDP + n0 + 16 * j, acc[i][j],
                                    LDP, wmma::mem_row_major);
    __syncthreads();
    // bias + scale + tf32 rounding, vectorized
    for (int idx = tid; idx < 4096; idx += 512) {
        int r = idx >> 6, c = (idx & 63) * 4;
        float4 v = *reinterpret_cast<float4*>(C + r * LDP + c);
        v.x = r32((v.x + bias[c + 0]) * scale);
        v.y = r32((v.y + bias[c + 1]) * scale);
        v.z = r32((v.z + bias[c + 2]) * scale);
        v.w = r32((v.w + bias[c + 3]) * scale);
        *reinterpret_cast<float4*>(C + r * LDP + c) = v;
    }
    __syncthreads();
}

// GQA attention: Q[64x256] (pre-scaled), KV[64x256] (K cols 0..127, V cols 128..255)
// -> AO[64x256]. 512 threads.
__device__ __forceinline__ void attention(const float* Q, const float* KV, float* AO,
                                          float* sc, int tid) {
    int warp = tid >> 5;
    for (int h = 0; h < 8; ++h) {
        int qo = h * 32;
        int ko = (h >> 1) * 32;
        int vo = 128 + (h >> 1) * 32;
        // ---- scores = Q_h @ K_h^T  (16 tiles of 16x16, 1 per warp)
        {
            int m0 = (warp & 3) * 16, n0 = (warp >> 2) * 16;
            wmma::fragment<wmma::accumulator, 16, 16, 8, float> acc;
            wmma::fill_fragment(acc, 0.0f);
#pragma unroll
            for (int k = 0; k < 4; ++k) {
                wmma::fragment<wmma::matrix_a, 16, 16, 8, wmma::precision::tf32, wmma::row_major> a;
                wmma::load_matrix_sync(a, Q + m0 * LDP + qo + k * 8, LDP);
                wmma::fragment<wmma::matrix_b, 16, 16, 8, wmma::precision::tf32, wmma::col_major> bf;
                wmma::load_matrix_sync(bf, KV + n0 * LDP + ko + k * 8, LDP);
                wmma::mma_sync(acc, a, bf, acc);
            }
            wmma::store_matrix_sync(sc + m0 * SPITCH + n0, acc, SPITCH, wmma::mem_row_major);
        }
        __syncthreads();
        // ---- row softmax: 8 lanes per row, 8 cols each
        {
            float* srow = sc + (tid >> 3) * SPITCH + (tid & 7) * 8;
            float4* sr4 = reinterpret_cast<float4*>(srow);
            float v[8];
            float4 t0 = sr4[0], t1 = sr4[1];
            v[0] = t0.x; v[1] = t0.y; v[2] = t0.z; v[3] = t0.w;
            v[4] = t1.x; v[5] = t1.y; v[6] = t1.z; v[7] = t1.w;
            float mx = v[0];
#pragma unroll
            for (int i = 1; i < 8; ++i) mx = fmaxf(mx, v[i]);
            mx = fmaxf(mx, __shfl_xor_sync(0xffffffffu, mx, 1));
            mx = fmaxf(mx, __shfl_xor_sync(0xffffffffu, mx, 2));
            mx = fmaxf(mx, __shfl_xor_sync(0xffffffffu, mx, 4));
            float sum = 0.0f;
#pragma unroll
            for (int i = 0; i < 8; ++i) { v[i] = __expf(v[i] - mx); sum += v[i]; }
            sum += __shfl_xor_sync(0xffffffffu, sum, 1);
            sum += __shfl_xor_sync(0xffffffffu, sum, 2);
            sum += __shfl_xor_sync(0xffffffffu, sum, 4);
            float inv = 1.0f / sum;
            t0.x = r32(v[0] * inv); t0.y = r32(v[1] * inv);
            t0.z = r32(v[2] * inv); t0.w = r32(v[3] * inv);
            t1.x = r32(v[4] * inv); t1.y = r32(v[5] * inv);
            t1.z = r32(v[6] * inv); t1.w = r32(v[7] * inv);
            sr4[0] = t0; sr4[1] = t1;
        }
        __syncthreads();
        // ---- AO_h = P @ V_h  (8 tiles of 16x16, warps 0..7)
        if (warp < 8) {
            int m0 = (warp >> 1) * 16, n0 = (warp & 1) * 16;
            wmma::fragment<wmma::accumulator, 16, 16, 8, float> acc;
            wmma::fill_fragment(acc, 0.0f);
#pragma unroll
            for (int k = 0; k < 8; ++k) {
                wmma::fragment<wmma::matrix_a, 16, 16, 8, wmma::precision::tf32, wmma::row_major> a;
                wmma::load_matrix_sync(a, sc + m0 * SPITCH + k * 8, SPITCH);
                wmma::fragment<wmma::matrix_b, 16, 16, 8, wmma::precision::tf32, wmma::row_major> bf;
                wmma::load_matrix_sync(bf, KV + (k * 8) * LDP + vo + n0, LDP);
                wmma::mma_sync(acc, a, bf, acc);
            }
            wmma::store_matrix_sync(AO + m0 * LDP + qo + n0, acc, LDP, wmma::mem_row_major);
        }
        __syncthreads();
    }
}

// ---------------- main fused kernel: 1 CTA per (sequence, branch) -----------------
__global__ void __launch_bounds__(512, 1)
fusion_kernel(const float* __restrict__ xspec, const float* __restrict__ xspat,
              const float* __restrict__ Wo0, const float* __restrict__ bo0,
              const float* __restrict__ Wo1, const float* __restrict__ bo1,
              const float* __restrict__ gate0, const float* __restrict__ gate1,
              float* __restrict__ out) {
    extern __shared__ float sm[];
    float* bufA  = sm;                 // x_hat  -> attn out
    float* bufQ  = sm + 64 * LDP;      // Q      -> O-proj result
    float* bufKV = sm + 2 * 64 * LDP;  // K | V
    float* aux   = sm + 3 * 64 * LDP;  // weight panels / score buffer (aliased)

    int tid = threadIdx.x;
    int br = blockIdx.x & 1;
    int bc = blockIdx.x >> 1;
    int b = bc >> 7, c = bc & 127;
    int base = (b * 8192 + c) * 256;   // [B,S,C,D] token (b, s=0, c)

    const float* xq  = br ? xspat : xspec;
    const float* xkv = br ? xspec : xspat;
    const float* Wq  = g_Wq[br];
    const float* Wkv = g_Wkv[br];
    const float* bq  = g_bq[br];
    const float* bkv = g_bkv[br];
    const float* Wo  = br ? Wo1 : Wo0;
    const float* bo  = br ? bo1 : bo0;
    float gv = br ? gate1[0] : gate0[0];
    float sg = 1.0f / (1.0f + __expf(-gv));
    float* outb = out + (br ? OUT_HALF : 0);

    // 1) KV path: x_hat(kv) -> [K|V]
    ln_rows(bufA, xkv + base, tid);
    __syncthreads();
    gemm64x256(bufA, Wkv, bkv, bufKV, aux, tid, 1.0f);

    // 2) Q path: x_hat(q) -> Q (pre-scaled by 1/sqrt(32))
    ln_rows(bufA, xq + base, tid);
    __syncthreads();
    gemm64x256(bufA, Wq, bq, bufQ, aux, tid, 0.17677669529663687f);

    // 3) attention (writes bufA = attn output)
    attention(bufQ, bufKV, bufA, aux, tid);

    // 4) output projection: delta = AO @ Wo + bo  (into bufQ)
    gemm64x256(bufA, Wo, bo, bufQ, aux, tid, 1.0f);

    // 5) epilogue: out = x + sigmoid(gate) * delta (coalesced, float4)
    for (int i = tid; i < 4096; i += 512) {
        int r = i >> 6, cc = (i & 63) * 4;
        int off = base + r * 32768 + cc;
        float4 x = *reinterpret_cast<const float4*>(xq + off);
        float4 d = *reinterpret_cast<const float4*>(bufQ + r * LDP + cc);
        x.x += sg * d.x; x.y += sg * d.y; x.z += sg * d.z; x.w += sg * d.w;
        *reinterpret_cast<float4*>(outb + off) = x;
    }
}

// ---------------- host launcher -----------------------------------------------------
extern "C" void kernel_launch(void* const* d_in, const int* in_sizes, int n_in,
                              void* d_out, int out_size) {
    const float* xspec = (const float*)d_in[0];
    const float* xspat = (const float*)d_in[1];
    const float* lsqg  = (const float*)d_in[2];
    const float* lsqb  = (const float*)d_in[3];
    const float* lskvg = (const float*)d_in[4];
    const float* lskvb = (const float*)d_in[5];
    const float* ltqg  = (const float*)d_in[6];
    const float* ltqb  = (const float*)d_in[7];
    const float* ltkvg = (const float*)d_in[8];
    const float* ltkvb = (const float*)d_in[9];
    const float* Wq0 = (const float*)d_in[10]; const float* bq0 = (const float*)d_in[11];
    const float* Wk0 = (const float*)d_in[12]; const float* bk0 = (const float*)d_in[13];
    const float* Wv0 = (const float*)d_in[14]; const float* bv0 = (const float*)d_in[15];
    const float* Wo0 = (const float*)d_in[16]; const float* bo0 = (const float*)d_in[17];
    const float* Wq1 = (const float*)d_in[18]; const float* bq1 = (const float*)d_in[19];
    const float* Wk1 = (const float*)d_in[20]; const float* bk1 = (const float*)d_in[21];
    const float* Wv1 = (const float*)d_in[22]; const float* bv1 = (const float*)d_in[23];
    const float* Wo1 = (const float*)d_in[24]; const float* bo1 = (const float*)d_in[25];
    const float* g0  = (const float*)d_in[26];
    const float* g1  = (const float*)d_in[27];
    float* out = (float*)d_out;

    // branch 0 (s2t): q-norm = spec_q, kv-norm = spat_kv
    // branch 1 (t2s): q-norm = spat_q, kv-norm = spec_kv
    prep_weights<<<1024, 256>>>(lsqg, ltkvg, ltqg, lskvg,
                                Wq0, Wk0, Wv0, Wq1, Wk1, Wv1);
    prep_bias<<<4, 256>>>(lsqb, ltkvb, ltqb, lskvb,
                          Wq0, Wk0, Wv0, bq0, bk0, bv0,
                          Wq1, Wk1, Wv1, bq1, bk1, bv1);

    const int SMEM = (3 * 64 * LDP + 64 * SPITCH) * 4;  // 221184 bytes
    cudaFuncSetAttribute(fusion_kernel, cudaFuncAttributeMaxDynamicSharedMemorySize, SMEM);
    fusion_kernel<<<2048, 512, SMEM>>>(xspec, xspat, Wo0, bo0, Wo1, bo1, g0, g1, out);
}

// round 5
// speedup vs baseline: 2.6803x; 2.2439x over previous
#include <cuda_runtime.h>
#include <cuda_fp16.h>
#include <mma.h>

using namespace nvcuda;

#define OUT_HALF 16777216           // 8*64*128*256
#define LDH   264                   // half pitch for 64x256 half buffers
#define PP    264                   // panel pitch (halves)
#define SP    68                    // score pitch (floats)
#define PHP   72                    // P pitch (halves)
#define S2P   36                    // PV scratch pitch (floats)

#define HA_OFF   0
#define HQ_OFF   33792
#define HKV_OFF  67584
#define AUX_OFF  101376
#define SMEM_BYTES 135168

// ---------------- folded weights (half) + biases (float) ---------------------------
__device__ __half g_Wq[2][65536];   // [k*256+n], gamma-q folded, *1/sqrt(32)
__device__ __half g_Wkv[2][65536];  // [k*256+n], [K|V], gamma-kv folded
__device__ __half g_Wo[2][65536];   // [k*256+n]
__device__ float  g_bq[2][256];     // (beta_q @ Wq + bq) * 1/sqrt(32)
__device__ float  g_bkv[2][256];

#define QS 0.17677669529663687f

// ---------------- single prep kernel ------------------------------------------------
__global__ void prep_all(const float* __restrict__ gq0, const float* __restrict__ gkv0,
                         const float* __restrict__ gq1, const float* __restrict__ gkv1,
                         const float* __restrict__ bqn0, const float* __restrict__ bkvn0,
                         const float* __restrict__ bqn1, const float* __restrict__ bkvn1,
                         const float* __restrict__ Wq0, const float* __restrict__ bq0,
                         const float* __restrict__ Wk0, const float* __restrict__ bk0,
                         const float* __restrict__ Wv0, const float* __restrict__ bv0,
                         const float* __restrict__ Wo0,
                         const float* __restrict__ Wq1, const float* __restrict__ bq1,
                         const float* __restrict__ Wk1, const float* __restrict__ bk1,
                         const float* __restrict__ Wv1, const float* __restrict__ bv1,
                         const float* __restrict__ Wo1) {
    int gid = blockIdx.x * blockDim.x + threadIdx.x;
    if (gid < 393216) {
        int br = gid / 196608, rem = gid - br * 196608;
        int mat = rem >> 16, e = rem & 65535;
        int k = e >> 8, n = e & 255;
        if (mat == 0) {
            const float* gq = br ? gq1 : gq0; const float* Wq = br ? Wq1 : Wq0;
            g_Wq[br][e] = __float2half_rn(gq[k] * Wq[e] * QS);
        } else if (mat == 1) {
            const float* gkv = br ? gkv1 : gkv0;
            const float* Wk = br ? Wk1 : Wk0; const float* Wv = br ? Wv1 : Wv0;
            float w = (n < 128) ? Wk[k * 128 + n] : Wv[k * 128 + n - 128];
            g_Wkv[br][e] = __float2half_rn(gkv[k] * w);
        } else {
            const float* Wo = br ? Wo1 : Wo0;
            g_Wo[br][e] = __float2half_rn(Wo[e]);
        }
    } else if (gid < 394240) {
        int t = gid - 393216;
        int br = t >> 9, tt = t & 511;
        const float* bqn = br ? bqn1 : bqn0; const float* bkvn = br ? bkvn1 : bkvn0;
        const float* Wq = br ? Wq1 : Wq0; const float* Wk = br ? Wk1 : Wk0;
        const float* Wv = br ? Wv1 : Wv0;
        const float* bq = br ? bq1 : bq0; const float* bk = br ? bk1 : bk0;
        const float* bv = br ? bv1 : bv0;
        if (tt < 256) {
            float a = bq[tt];
            for (int k = 0; k < 256; ++k) a += bqn[k] * Wq[k * 256 + tt];
            g_bq[br][tt] = a * QS;
        } else if (tt < 384) {
            int c = tt - 256; float a = bk[c];
            for (int k = 0; k < 256; ++k) a += bkvn[k] * Wk[k * 128 + c];
            g_bkv[br][c] = a;
        } else {
            int c = tt - 384; float a = bv[c];
            for (int k = 0; k < 256; ++k) a += bkvn[k] * Wv[k * 128 + c];
            g_bkv[br][c + 128] = a;
        }
    }
}

// ---------------- LN -> half smem ---------------------------------------------------
__device__ __forceinline__ void ln_rows(__half* dst, const float* __restrict__ src, int tid) {
    int warp = tid >> 5, lane = tid & 31;
    for (int r = warp; r < 64; r += 16) {
        const float* rp = src + r * 32768;
        float4 u = *reinterpret_cast<const float4*>(rp + lane * 8);
        float4 v = *reinterpret_cast<const float4*>(rp + lane * 8 + 4);
        float s = u.x + u.y + u.z + u.w + v.x + v.y + v.z + v.w;
        float q = u.x * u.x + u.y * u.y + u.z * u.z + u.w * u.w +
                  v.x * v.x + v.y * v.y + v.z * v.z + v.w * v.w;
#pragma unroll
        for (int o = 16; o; o >>= 1) {
            s += __shfl_xor_sync(0xffffffffu, s, o);
            q += __shfl_xor_sync(0xffffffffu, q, o);
        }
        float mu = s * (1.0f / 256.0f);
        float rs = rsqrtf(q * (1.0f / 256.0f) - mu * mu + 1e-5f);
        uint4 pk;
        __half2* ph = reinterpret_cast<__half2*>(&pk);
        ph[0] = __floats2half2_rn((u.x - mu) * rs, (u.y - mu) * rs);
        ph[1] = __floats2half2_rn((u.z - mu) * rs, (u.w - mu) * rs);
        ph[2] = __floats2half2_rn((v.x - mu) * rs, (v.y - mu) * rs);
        ph[3] = __floats2half2_rn((v.z - mu) * rs, (v.w - mu) * rs);
        *reinterpret_cast<uint4*>(dst + r * LDH + lane * 8) = pk;
    }
}

// ---------------- GEMM: C[64x256] = A @ W + bias ------------------------------------
// MODE 0: convert C to half -> dsth. MODE 1: out = x + sg*(C + bias), write gmem.
template <int MODE>
__device__ __forceinline__ void gemm64x256h(const __half* A, const __half* __restrict__ Wg,
                                            const float* __restrict__ bias, __half* dsth,
                                            char* smc, int tid,
                                            const float* xq, float* outb, int cbase, float sg) {
    int w = tid >> 5;
    int m0 = (w & 1) * 32, n0 = (w >> 1) * 32;
    __half* p0 = reinterpret_cast<__half*>(smc + AUX_OFF);
    __half* p1 = reinterpret_cast<__half*>(smc + AUX_OFF + 16896);
    float* auxf = reinterpret_cast<float*>(smc + AUX_OFF);
    int pr = tid >> 4, pc = (tid & 15) * 16;

    wmma::fragment<wmma::accumulator, 16, 16, 16, float> acc[2][2];
#pragma unroll
    for (int i = 0; i < 2; ++i)
#pragma unroll
        for (int j = 0; j < 2; ++j) wmma::fill_fragment(acc[i][j], 0.0f);

    {   // stage panel 0
        const uint4* s = reinterpret_cast<const uint4*>(Wg + pr * 256 + pc);
        uint4* d = reinterpret_cast<uint4*>(p0 + pr * PP + pc);
        d[0] = s[0]; d[1] = s[1];
    }
    __syncthreads();

    for (int st = 0; st < 8; ++st) {
        uint4 nx0, nx1;
        if (st < 7) {
            const uint4* s = reinterpret_cast<const uint4*>(Wg + ((st + 1) * 32 + pr) * 256 + pc);
            nx0 = s[0]; nx1 = s[1];
        }
        const __half* cur = (st & 1) ? p1 : p0;
#pragma unroll
        for (int kk = 0; kk < 2; ++kk) {
            wmma::fragment<wmma::matrix_a, 16, 16, 16, __half, wmma::row_major> a[2];
            wmma::load_matrix_sync(a[0], A + m0 * LDH + st * 32 + kk * 16, LDH);
            wmma::load_matrix_sync(a[1], A + (m0 + 16) * LDH + st * 32 + kk * 16, LDH);
            wmma::fragment<wmma::matrix_b, 16, 16, 16, __half, wmma::row_major> b[2];
            wmma::load_matrix_sync(b[0], cur + (kk * 16) * PP + n0, PP);
            wmma::load_matrix_sync(b[1], cur + (kk * 16) * PP + n0 + 16, PP);
#pragma unroll
            for (int i = 0; i < 2; ++i)
#pragma unroll
                for (int j = 0; j < 2; ++j) wmma::mma_sync(acc[i][j], a[i], b[j], acc[i][j]);
        }
        if (st < 7) {
            uint4* d = reinterpret_cast<uint4*>(((st & 1) ? p0 : p1) + pr * PP + pc);
            d[0] = nx0; d[1] = nx1;
        }
        __syncthreads();
    }

    // epilogue: 4 rounds of 64-col chunks through fp32 aux
    int erow = tid >> 3, ec = (tid & 7) * 8;
#pragma unroll
    for (int r = 0; r < 4; ++r) {
        if ((w >> 2) == r) {
#pragma unroll
            for (int i = 0; i < 2; ++i)
#pragma unroll
                for (int j = 0; j < 2; ++j)
                    wmma::store_matrix_sync(auxf + (m0 + 16 * i) * SP + (n0 & 63) + 16 * j,
                                            acc[i][j], SP, wmma::mem_row_major);
        }
        __syncthreads();
        const float* sp = auxf + erow * SP + ec;
        const float* bb = bias + r * 64 + ec;
        if (MODE == 0) {
            uint4 pk;
            __half2* ph = reinterpret_cast<__half2*>(&pk);
            ph[0] = __floats2half2_rn(sp[0] + bb[0], sp[1] + bb[1]);
            ph[1] = __floats2half2_rn(sp[2] + bb[2], sp[3] + bb[3]);
            ph[2] = __floats2half2_rn(sp[4] + bb[4], sp[5] + bb[5]);
            ph[3] = __floats2half2_rn(sp[6] + bb[6], sp[7] + bb[7]);
            *reinterpret_cast<uint4*>(dsth + erow * LDH + r * 64 + ec) = pk;
        } else {
            int off = cbase + erow * 32768 + r * 64 + ec;
            float4 x1 = *reinterpret_cast<const float4*>(xq + off);
            float4 x2 = *reinterpret_cast<const float4*>(xq + off + 4);
            float4 o1, o2;
            o1.x = x1.x + sg * (sp[0] + bb[0]); o1.y = x1.y + sg * (sp[1] + bb[1]);
            o1.z = x1.z + sg * (sp[2] + bb[2]); o1.w = x1.w + sg * (sp[3] + bb[3]);
            o2.x = x2.x + sg * (sp[4] + bb[4]); o2.y = x2.y + sg * (sp[5] + bb[5]);
            o2.z = x2.z + sg * (sp[6] + bb[6]); o2.w = x2.w + sg * (sp[7] + bb[7]);
            *reinterpret_cast<float4*>(outb + off) = o1;
            *reinterpret_cast<float4*>(outb + off + 4) = o2;
        }
        __syncthreads();
    }
}

// ---------------- attention ---------------------------------------------------------
__device__ __forceinline__ void attention(const __half* Q, const __half* KV, __half* AO,
                                          char* smc, int tid) {
    int w = tid >> 5;
    float* scf = reinterpret_cast<float*>(smc + AUX_OFF);
    __half* Ph = reinterpret_cast<__half*>(smc + AUX_OFF + 17408);
    int row = tid >> 3, seg = (tid & 7) * 8;

    for (int h = 0; h < 8; ++h) {
        int qo = h * 32, ko = (h >> 1) * 32, vo = 128 + (h >> 1) * 32;
        // scores = Q_h @ K_h^T (Q pre-scaled)
        {
            int m0 = (w & 3) * 16, n0 = (w >> 2) * 16;
            wmma::fragment<wmma::accumulator, 16, 16, 16, float> acc;
            wmma::fill_fragment(acc, 0.0f);
#pragma unroll
            for (int kk = 0; kk < 2; ++kk) {
                wmma::fragment<wmma::matrix_a, 16, 16, 16, __half, wmma::row_major> a;
                wmma::load_matrix_sync(a, Q + m0 * LDH + qo + kk * 16, LDH);
                wmma::fragment<wmma::matrix_b, 16, 16, 16, __half, wmma::col_major> b;
                wmma::load_matrix_sync(b, KV + n0 * LDH + ko + kk * 16, LDH);
                wmma::mma_sync(acc, a, b, acc);
            }
            wmma::store_matrix_sync(scf + m0 * SP + n0, acc, SP, wmma::mem_row_major);
        }
        __syncthreads();
        // softmax: 8 lanes per row, 8 cols each (lanes of a row share a warp octet)
        {
            const float* sr = scf + row * SP + seg;
            float v0 = sr[0], v1 = sr[1], v2 = sr[2], v3 = sr[3];
            float v4 = sr[4], v5 = sr[5], v6 = sr[6], v7 = sr[7];
            float mx = fmaxf(fmaxf(fmaxf(v0, v1), fmaxf(v2, v3)),
                             fmaxf(fmaxf(v4, v5), fmaxf(v6, v7)));
            mx = fmaxf(mx, __shfl_xor_sync(0xffffffffu, mx, 1));
            mx = fmaxf(mx, __shfl_xor_sync(0xffffffffu, mx, 2));
            mx = fmaxf(mx, __shfl_xor_sync(0xffffffffu, mx, 4));
            v0 = __expf(v0 - mx); v1 = __expf(v1 - mx); v2 = __expf(v2 - mx); v3 = __expf(v3 - mx);
            v4 = __expf(v4 - mx); v5 = __expf(v5 - mx); v6 = __expf(v6 - mx); v7 = __expf(v7 - mx);
            float sum = v0 + v1 + v2 + v3 + v4 + v5 + v6 + v7;
            sum += __shfl_xor_sync(0xffffffffu, sum, 1);
            sum += __shfl_xor_sync(0xffffffffu, sum, 2);
            sum += __shfl_xor_sync(0xffffffffu, sum, 4);
            float inv = 1.0f / sum;
            uint4 pk;
            __half2* ph = reinterpret_cast<__half2*>(&pk);
            ph[0] = __floats2half2_rn(v0 * inv, v1 * inv);
            ph[1] = __floats2half2_rn(v2 * inv, v3 * inv);
            ph[2] = __floats2half2_rn(v4 * inv, v5 * inv);
            ph[3] = __floats2half2_rn(v6 * inv, v7 * inv);
            *reinterpret_cast<uint4*>(Ph + row * PHP + seg) = pk;
        }
        __syncthreads();
        // AO_h = P @ V_h  (warps 0..7)
        if (w < 8) {
            int m0 = (w >> 1) * 16, n0 = (w & 1) * 16;
            wmma::fragment<wmma::accumulator, 16, 16, 16, float> acc;
            wmma::fill_fragment(acc, 0.0f);
#pragma unroll
            for (int k4 = 0; k4 < 4; ++k4) {
                wmma::fragment<wmma::matrix_a, 16, 16, 16, __half, wmma::row_major> a;
                wmma::load_matrix_sync(a, Ph + m0 * PHP + k4 * 16, PHP);
                wmma::fragment<wmma::matrix_b, 16, 16, 16, __half, wmma::row_major> b;
                wmma::load_matrix_sync(b, KV + (k4 * 16) * LDH + vo + n0, LDH);
                wmma::mma_sync(acc, a, b, acc);
            }
            wmma::store_matrix_sync(scf + m0 * S2P + n0, acc, S2P, wmma::mem_row_major);
        }
        __syncthreads();
        // convert AO chunk to half (64x32)
        {
            int c4 = (tid & 7) * 4;
            const float* sp = scf + row * S2P + c4;
            uint2 pk;
            __half2* ph = reinterpret_cast<__half2*>(&pk);
            ph[0] = __floats2half2_rn(sp[0], sp[1]);
            ph[1] = __floats2half2_rn(sp[2], sp[3]);
            *reinterpret_cast<uint2*>(AO + row * LDH + qo + c4) = pk;
        }
        __syncthreads();
    }
}

// ---------------- main fused kernel --------------------------------------------------
__global__ void __launch_bounds__(512, 1)
fusion_kernel(const float* __restrict__ xspec, const float* __restrict__ xspat,
              const float* __restrict__ bo0, const float* __restrict__ bo1,
              const float* __restrict__ gate0, const float* __restrict__ gate1,
              float* __restrict__ out) {
    extern __shared__ char smc[];
    __half* hA  = reinterpret_cast<__half*>(smc + HA_OFF);
    __half* hQ  = reinterpret_cast<__half*>(smc + HQ_OFF);
    __half* hKV = reinterpret_cast<__half*>(smc + HKV_OFF);

    int tid = threadIdx.x;
    int br = blockIdx.x & 1;
    int bc = blockIdx.x >> 1;
    int b = bc >> 7, c = bc & 127;
    int cbase = (b * 8192 + c) * 256;

    const float* xq  = br ? xspat : xspec;
    const float* xkv = br ? xspec : xspat;
    const float* bo  = br ? bo1 : bo0;
    float gv = br ? gate1[0] : gate0[0];
    float sg = 1.0f / (1.0f + __expf(-gv));
    float* outb = out + (br ? OUT_HALF : 0);

    // 1) KV path
    ln_rows(hA, xkv + cbase, tid);
    __syncthreads();
    gemm64x256h<0>(hA, g_Wkv[br], g_bkv[br], hKV, smc, tid, nullptr, nullptr, 0, 0.f);

    // 2) Q path (scale folded into weights/bias)
    ln_rows(hA, xq + cbase, tid);
    __syncthreads();
    gemm64x256h<0>(hA, g_Wq[br], g_bq[br], hQ, smc, tid, nullptr, nullptr, 0, 0.f);

    // 3) attention -> AO in hA
    attention(hQ, hKV, hA, smc, tid);

    // 4) O projection + residual epilogue (writes out directly, fp32 path)
    gemm64x256h<1>(hA, g_Wo[br], bo, nullptr, smc, tid, xq, outb, cbase, sg);
}

// ---------------- host launcher -------------------------------------------------------
extern "C" void kernel_launch(void* const* d_in, const int* in_sizes, int n_in,
                              void* d_out, int out_size) {
    const float* xspec = (const float*)d_in[0];
    const float* xspat = (const float*)d_in[1];
    const float* lsqg  = (const float*)d_in[2];
    const float* lsqb  = (const float*)d_in[3];
    const float* lskvg = (const float*)d_in[4];
    const float* lskvb = (const float*)d_in[5];
    const float* ltqg  = (const float*)d_in[6];
    const float* ltqb  = (const float*)d_in[7];
    const float* ltkvg = (const float*)d_in[8];
    const float* ltkvb = (const float*)d_in[9];
    const float* Wq0 = (const float*)d_in[10]; const float* bq0 = (const float*)d_in[11];
    const float* Wk0 = (const float*)d_in[12]; const float* bk0 = (const float*)d_in[13];
    const float* Wv0 = (const float*)d_in[14]; const float* bv0 = (const float*)d_in[15];
    const float* Wo0 = (const float*)d_in[16]; const float* bo0 = (const float*)d_in[17];
    const float* Wq1 = (const float*)d_in[18]; const float* bq1 = (const float*)d_in[19];
    const float* Wk1 = (const float*)d_in[20]; const float* bk1 = (const float*)d_in[21];
    const float* Wv1 = (const float*)d_in[22]; const float* bv1 = (const float*)d_in[23];
    const float* Wo1 = (const float*)d_in[24]; const float* bo1 = (const float*)d_in[25];
    const float* g0  = (const float*)d_in[26];
    const float* g1  = (const float*)d_in[27];
    float* out = (float*)d_out;

    // branch 0 (s2t): q-norm=spec_q, kv-norm=spat_kv; branch 1 (t2s): q-norm=spat_q, kv-norm=spec_kv
    prep_all<<<1540, 256>>>(lsqg, ltkvg, ltqg, lskvg,
                            lsqb, ltkvb, ltqb, lskvb,
                            Wq0, bq0, Wk0, bk0, Wv0, bv0, Wo0,
                            Wq1, bq1, Wk1, bk1, Wv1, bv1, Wo1);

    cudaFuncSetAttribute(fusion_kernel, cudaFuncAttributeMaxDynamicSharedMemorySize, SMEM_BYTES);
    fusion_kernel<<<2048, 512, SMEM_BYTES>>>(xspec, xspat, bo0, bo1, g0, g1, out);
}

// round 6
// speedup vs baseline: 3.0922x; 1.1537x over previous
#include <cuda_runtime.h>
#include <cuda_fp16.h>
#include <mma.h>

using namespace nvcuda;

#define OUT_HALF 16777216           // 8*64*128*256
#define LDH   264                   // half pitch, 128-row buffers (528B rows, 16B aligned)
#define PP    264                   // panel pitch (halves)
#define SCP   68                    // score/aux pitch (floats)
#define PHP   72                    // P pitch (halves)
#define AOP   36                    // PV scratch pitch (floats)

#define BUF1_OFF 0                  // 128*264*2 = 67584: x_kv -> KV
#define BUF2_OFF 67584              // x_q -> Q -> AO
#define AUX_OFF  135168             // 34816: panels (2x16896) / scores 128x68 f32 / AO scratch
#define P_OFF    169984             // 18432: P half 128x72
#define SMEM_BYTES 188416

// ---------------- folded weights (half) + biases (float) ---------------------------
__device__ __half g_Wq[2][65536];   // [k*256+n], gamma-q folded, *1/sqrt(32)
__device__ __half g_Wkv[2][65536];  // [k*256+n], [K|V], gamma-kv folded
__device__ __half g_Wo[2][65536];   // [k*256+n]
__device__ float  g_bq[2][256];
__device__ float  g_bkv[2][256];

#define QS 0.17677669529663687f

// ---------------- single prep kernel ------------------------------------------------
__global__ void prep_all(const float* __restrict__ gq0, const float* __restrict__ gkv0,
                         const float* __restrict__ gq1, const float* __restrict__ gkv1,
                         const float* __restrict__ bqn0, const float* __restrict__ bkvn0,
                         const float* __restrict__ bqn1, const float* __restrict__ bkvn1,
                         const float* __restrict__ Wq0, const float* __restrict__ bq0,
                         const float* __restrict__ Wk0, const float* __restrict__ bk0,
                         const float* __restrict__ Wv0, const float* __restrict__ bv0,
                         const float* __restrict__ Wo0,
                         const float* __restrict__ Wq1, const float* __restrict__ bq1,
                         const float* __restrict__ Wk1, const float* __restrict__ bk1,
                         const float* __restrict__ Wv1, const float* __restrict__ bv1,
                         const float* __restrict__ Wo1) {
    int gid = blockIdx.x * blockDim.x + threadIdx.x;
    if (gid < 393216) {
        int br = gid / 196608, rem = gid - br * 196608;
        int mat = rem >> 16, e = rem & 65535;
        int k = e >> 8, n = e & 255;
        if (mat == 0) {
            const float* gq = br ? gq1 : gq0; const float* Wq = br ? Wq1 : Wq0;
            g_Wq[br][e] = __float2half_rn(gq[k] * Wq[e] * QS);
        } else if (mat == 1) {
            const float* gkv = br ? gkv1 : gkv0;
            const float* Wk = br ? Wk1 : Wk0; const float* Wv = br ? Wv1 : Wv0;
            float w = (n < 128) ? Wk[k * 128 + n] : Wv[k * 128 + n - 128];
            g_Wkv[br][e] = __float2half_rn(gkv[k] * w);
        } else {
            const float* Wo = br ? Wo1 : Wo0;
            g_Wo[br][e] = __float2half_rn(Wo[e]);
        }
    } else if (gid < 394240) {
        int t = gid - 393216;
        int br = t >> 9, tt = t & 511;
        const float* bqn = br ? bqn1 : bqn0; const float* bkvn = br ? bkvn1 : bkvn0;
        const float* Wq = br ? Wq1 : Wq0; const float* Wk = br ? Wk1 : Wk0;
        const float* Wv = br ? Wv1 : Wv0;
        const float* bq = br ? bq1 : bq0; const float* bk = br ? bk1 : bk0;
        const float* bv = br ? bv1 : bv0;
        if (tt < 256) {
            float a = bq[tt];
            for (int k = 0; k < 256; ++k) a += bqn[k] * Wq[k * 256 + tt];
            g_bq[br][tt] = a * QS;
        } else if (tt < 384) {
            int c = tt - 256; float a = bk[c];
            for (int k = 0; k < 256; ++k) a += bkvn[k] * Wk[k * 128 + c];
            g_bkv[br][c] = a;
        } else {
            int c = tt - 384; float a = bv[c];
            for (int k = 0; k < 256; ++k) a += bkvn[k] * Wv[k * 128 + c];
            g_bkv[br][c + 128] = a;
        }
    }
}

// ---------------- main fused kernel: 1 CTA = 2 sequences, 1 branch ------------------
__global__ void __launch_bounds__(512, 1)
fusion_kernel(const float* __restrict__ xspec, const float* __restrict__ xspat,
              const float* __restrict__ bo0, const float* __restrict__ bo1,
              const float* __restrict__ gate0, const float* __restrict__ gate1,
              float* __restrict__ out) {
    extern __shared__ char smc[];
    __half* buf1 = reinterpret_cast<__half*>(smc + BUF1_OFF);
    __half* buf2 = reinterpret_cast<__half*>(smc + BUF2_OFF);
    __half* p0   = reinterpret_cast<__half*>(smc + AUX_OFF);
    __half* p1   = reinterpret_cast<__half*>(smc + AUX_OFF + 16896);
    float*  auxf = reinterpret_cast<float*>(smc + AUX_OFF);
    __half* Ph   = reinterpret_cast<__half*>(smc + P_OFF);

    int tid = threadIdx.x, w = tid >> 5;
    int br = blockIdx.x >> 9, pair = blockIdx.x & 511;

    const float* xq  = br ? xspat : xspec;
    const float* xkv = br ? xspec : xspat;
    const float* bo  = br ? bo1 : bo0;
    float gv = br ? gate1[0] : gate0[0];
    float sg = 1.0f / (1.0f + __expf(-gv));
    float* outb = out + (br ? OUT_HALF : 0);

    // row r (0..127) -> gmem base of that token row
    auto rbase = [&](int r) {
        int s = pair * 2 + (r >> 6);
        return ((s >> 7) * 8192 + (s & 127)) * 256 + (r & 63) * 32768;
    };

    // ---------- LN: 128 rows -> half buffer ----------
    auto ln_rows = [&](__half* dst, const float* __restrict__ src) {
        int lane = tid & 31;
        for (int r = w; r < 128; r += 16) {
            const float* rp = src + rbase(r);
            float4 u = *reinterpret_cast<const float4*>(rp + lane * 8);
            float4 v = *reinterpret_cast<const float4*>(rp + lane * 8 + 4);
            float s = u.x + u.y + u.z + u.w + v.x + v.y + v.z + v.w;
            float q = u.x * u.x + u.y * u.y + u.z * u.z + u.w * u.w +
                      v.x * v.x + v.y * v.y + v.z * v.z + v.w * v.w;
#pragma unroll
            for (int o = 16; o; o >>= 1) {
                s += __shfl_xor_sync(0xffffffffu, s, o);
                q += __shfl_xor_sync(0xffffffffu, q, o);
            }
            float mu = s * (1.0f / 256.0f);
            float rs = rsqrtf(q * (1.0f / 256.0f) - mu * mu + 1e-5f);
            uint4 pk;
            __half2* ph = reinterpret_cast<__half2*>(&pk);
            ph[0] = __floats2half2_rn((u.x - mu) * rs, (u.y - mu) * rs);
            ph[1] = __floats2half2_rn((u.z - mu) * rs, (u.w - mu) * rs);
            ph[2] = __floats2half2_rn((v.x - mu) * rs, (v.y - mu) * rs);
            ph[3] = __floats2half2_rn((v.z - mu) * rs, (v.w - mu) * rs);
            *reinterpret_cast<uint4*>(dst + r * LDH + lane * 8) = pk;
        }
    };

    // ---------- GEMM: C[128x256] = A @ W + bias; in-place C over A allowed ----------
    // MODE 0: C -> half into dsth. MODE 1: out = x + sg*(C+bias) to gmem.
    auto gemm128 = [&](const __half* A, const __half* __restrict__ Wg,
                       const float* __restrict__ bias, __half* dsth, int MODE) {
        int m0 = (w & 3) * 32, n0 = (w >> 2) * 64;
        int pr = tid >> 4, pc = (tid & 15) * 16;

        wmma::fragment<wmma::accumulator, 16, 16, 16, float> acc[2][4];
#pragma unroll
        for (int i = 0; i < 2; ++i)
#pragma unroll
            for (int j = 0; j < 4; ++j) wmma::fill_fragment(acc[i][j], 0.0f);

        {
            const uint4* s = reinterpret_cast<const uint4*>(Wg + pr * 256 + pc);
            uint4* d = reinterpret_cast<uint4*>(p0 + pr * PP + pc);
            d[0] = s[0]; d[1] = s[1];
        }
        __syncthreads();

        for (int st = 0; st < 8; ++st) {
            uint4 nx0, nx1;
            if (st < 7) {
                const uint4* s = reinterpret_cast<const uint4*>(Wg + ((st + 1) * 32 + pr) * 256 + pc);
                nx0 = s[0]; nx1 = s[1];
            }
            const __half* cur = (st & 1) ? p1 : p0;
#pragma unroll
            for (int kk = 0; kk < 2; ++kk) {
                wmma::fragment<wmma::matrix_a, 16, 16, 16, __half, wmma::row_major> a[2];
                wmma::load_matrix_sync(a[0], A + m0 * LDH + st * 32 + kk * 16, LDH);
                wmma::load_matrix_sync(a[1], A + (m0 + 16) * LDH + st * 32 + kk * 16, LDH);
#pragma unroll
                for (int j = 0; j < 4; ++j) {
                    wmma::fragment<wmma::matrix_b, 16, 16, 16, __half, wmma::row_major> b;
                    wmma::load_matrix_sync(b, cur + (kk * 16) * PP + n0 + j * 16, PP);
                    wmma::mma_sync(acc[0][j], a[0], b, acc[0][j]);
                    wmma::mma_sync(acc[1][j], a[1], b, acc[1][j]);
                }
            }
            if (st < 7) {
                uint4* d = reinterpret_cast<uint4*>(((st & 1) ? p0 : p1) + pr * PP + pc);
                d[0] = nx0; d[1] = nx1;
            }
            __syncthreads();
        }

        // epilogue: 4 rounds, each a 128x64 column chunk through fp32 aux
        int erow = tid >> 2, ec = (tid & 3) * 16;
#pragma unroll
        for (int r = 0; r < 4; ++r) {
            if ((w >> 2) == r) {
#pragma unroll
                for (int i = 0; i < 2; ++i)
#pragma unroll
                    for (int j = 0; j < 4; ++j)
                        wmma::store_matrix_sync(auxf + (m0 + 16 * i) * SCP + j * 16,
                                                acc[i][j], SCP, wmma::mem_row_major);
            }
            __syncthreads();
            const float* sp = auxf + erow * SCP + ec;
            const float* bb = bias + r * 64 + ec;
            if (MODE == 0) {
                uint4 pk[2];
                __half2* ph = reinterpret_cast<__half2*>(pk);
#pragma unroll
                for (int j = 0; j < 8; ++j)
                    ph[j] = __floats2half2_rn(sp[2 * j] + bb[2 * j], sp[2 * j + 1] + bb[2 * j + 1]);
                uint4* d = reinterpret_cast<uint4*>(dsth + erow * LDH + r * 64 + ec);
                d[0] = pk[0]; d[1] = pk[1];
            } else {
                int off = rbase(erow) + r * 64 + ec;
#pragma unroll
                for (int q4 = 0; q4 < 4; ++q4) {
                    float4 x = *reinterpret_cast<const float4*>(xq + off + q4 * 4);
                    float4 o;
                    o.x = x.x + sg * (sp[q4 * 4 + 0] + bb[q4 * 4 + 0]);
                    o.y = x.y + sg * (sp[q4 * 4 + 1] + bb[q4 * 4 + 1]);
                    o.z = x.z + sg * (sp[q4 * 4 + 2] + bb[q4 * 4 + 2]);
                    o.w = x.w + sg * (sp[q4 * 4 + 3] + bb[q4 * 4 + 3]);
                    *reinterpret_cast<float4*>(outb + off + q4 * 4) = o;
                }
            }
            __syncthreads();
        }
    };

    // ================= pipeline =================
    // 1) KV path: buf1 = LN(xkv); buf1 = [K|V] (in place)
    ln_rows(buf1, xkv);
    __syncthreads();
    gemm128(buf1, g_Wkv[br], g_bkv[br], buf1, 0);

    // 2) Q path: buf2 = LN(xq); buf2 = Q (scale folded)
    ln_rows(buf2, xq);
    __syncthreads();
    gemm128(buf2, g_Wq[br], g_bq[br], buf2, 0);

    // 3) attention: per head, scores both seq blocks; AO_h overwrites Q_h
    {
        int seqw = w >> 3, iw = w & 7;
        int msA = iw >> 1, npA = (iw & 1) * 2;        // QK: m-tile, n-tile pair
        int m0A = seqw * 64 + msA * 16;
        int srow = tid >> 2, seg = (tid & 3) * 16;    // softmax mapping
        int mtP = w >> 1, n0P = (w & 1) * 16;         // PV: 1 tile per warp
        int m0P = mtP * 16, seqP = mtP >> 2;
        int crow = tid >> 2, cc = (tid & 3) * 8;      // AO convert mapping

        for (int h = 0; h < 8; ++h) {
            int qo = h * 32, ko = (h >> 1) * 32, vo = 128 + (h >> 1) * 32;
            // ---- scores ----
            {
                wmma::fragment<wmma::accumulator, 16, 16, 16, float> acc[2];
                wmma::fill_fragment(acc[0], 0.0f);
                wmma::fill_fragment(acc[1], 0.0f);
#pragma unroll
                for (int kk = 0; kk < 2; ++kk) {
                    wmma::fragment<wmma::matrix_a, 16, 16, 16, __half, wmma::row_major> a;
                    wmma::load_matrix_sync(a, buf2 + m0A * LDH + qo + kk * 16, LDH);
#pragma unroll
                    for (int j = 0; j < 2; ++j) {
                        wmma::fragment<wmma::matrix_b, 16, 16, 16, __half, wmma::col_major> b;
                        wmma::load_matrix_sync(b, buf1 + (seqw * 64 + (npA + j) * 16) * LDH + ko + kk * 16, LDH);
                        wmma::mma_sync(acc[j], a, b, acc[j]);
                    }
                }
                wmma::store_matrix_sync(auxf + m0A * SCP + npA * 16, acc[0], SCP, wmma::mem_row_major);
                wmma::store_matrix_sync(auxf + m0A * SCP + (npA + 1) * 16, acc[1], SCP, wmma::mem_row_major);
            }
            __syncthreads();
            // ---- softmax: 4 threads per row, 16 cols each ----
            {
                const float* sr = auxf + srow * SCP + seg;
                float v[16];
#pragma unroll
                for (int i = 0; i < 4; ++i) {
                    float4 t = *reinterpret_cast<const float4*>(sr + i * 4);
                    v[4 * i] = t.x; v[4 * i + 1] = t.y; v[4 * i + 2] = t.z; v[4 * i + 3] = t.w;
                }
                float mx = v[0];
#pragma unroll
                for (int i = 1; i < 16; ++i) mx = fmaxf(mx, v[i]);
                mx = fmaxf(mx, __shfl_xor_sync(0xffffffffu, mx, 1));
                mx = fmaxf(mx, __shfl_xor_sync(0xffffffffu, mx, 2));
                float sum = 0.0f;
#pragma unroll
                for (int i = 0; i < 16; ++i) { v[i] = __expf(v[i] - mx); sum += v[i]; }
                sum += __shfl_xor_sync(0xffffffffu, sum, 1);
                sum += __shfl_xor_sync(0xffffffffu, sum, 2);
                float inv = 1.0f / sum;
                uint4 pk;
                __half2* ph = reinterpret_cast<__half2*>(&pk);
                ph[0] = __floats2half2_rn(v[0] * inv, v[1] * inv);
                ph[1] = __floats2half2_rn(v[2] * inv, v[3] * inv);
                ph[2] = __floats2half2_rn(v[4] * inv, v[5] * inv);
                ph[3] = __floats2half2_rn(v[6] * inv, v[7] * inv);
                __half2* ph2 = reinterpret_cast<__half2*>(&pk) + 4;  // second uint4 via two writes
                uint4 pk2;
                __half2* phb = reinterpret_cast<__half2*>(&pk2);
                phb[0] = __floats2half2_rn(v[8] * inv, v[9] * inv);
                phb[1] = __floats2half2_rn(v[10] * inv, v[11] * inv);
                phb[2] = __floats2half2_rn(v[12] * inv, v[13] * inv);
                phb[3] = __floats2half2_rn(v[14] * inv, v[15] * inv);
                uint4* d = reinterpret_cast<uint4*>(Ph + srow * PHP + seg);
                d[0] = pk; d[1] = pk2;
                (void)ph2;
            }
            __syncthreads();
            // ---- PV: AO_h = P @ V_h (1 tile per warp) ----
            {
                wmma::fragment<wmma::accumulator, 16, 16, 16, float> acc;
                wmma::fill_fragment(acc, 0.0f);
#pragma unroll
                for (int k4 = 0; k4 < 4; ++k4) {
                    wmma::fragment<wmma::matrix_a, 16, 16, 16, __half, wmma::row_major> a;
                    wmma::load_matrix_sync(a, Ph + m0P * PHP + k4 * 16, PHP);
                    wmma::fragment<wmma::matrix_b, 16, 16, 16, __half, wmma::row_major> b;
                    wmma::load_matrix_sync(b, buf1 + (seqP * 64 + k4 * 16) * LDH + vo + n0P, LDH);
                    wmma::mma_sync(acc, a, b, acc);
                }
                wmma::store_matrix_sync(auxf + m0P * AOP + n0P, acc, AOP, wmma::mem_row_major);
            }
            __syncthreads();
            // ---- AO chunk -> half over Q_h ----
            {
                const float* sp = auxf + crow * AOP + cc;
                uint4 pk;
                __half2* ph = reinterpret_cast<__half2*>(&pk);
                ph[0] = __floats2half2_rn(sp[0], sp[1]);
                ph[1] = __floats2half2_rn(sp[2], sp[3]);
                ph[2] = __floats2half2_rn(sp[4], sp[5]);
                ph[3] = __floats2half2_rn(sp[6], sp[7]);
                *reinterpret_cast<uint4*>(buf2 + crow * LDH + qo + cc) = pk;
            }
            __syncthreads();
        }
    }

    // 4) O projection + residual epilogue (A = AO in buf2)
    gemm128(buf2, g_Wo[br], bo, nullptr, 1);
}

// ---------------- host launcher -------------------------------------------------------
extern "C" void kernel_launch(void* const* d_in, const int* in_sizes, int n_in,
                              void* d_out, int out_size) {
    const float* xspec = (const float*)d_in[0];
    const float* xspat = (const float*)d_in[1];
    const float* lsqg  = (const float*)d_in[2];
    const float* lsqb  = (const float*)d_in[3];
    const float* lskvg = (const float*)d_in[4];
    const float* lskvb = (const float*)d_in[5];
    const float* ltqg  = (const float*)d_in[6];
    const float* ltqb  = (const float*)d_in[7];
    const float* ltkvg = (const float*)d_in[8];
    const float* ltkvb = (const float*)d_in[9];
    const float* Wq0 = (const float*)d_in[10]; const float* bq0 = (const float*)d_in[11];
    const float* Wk0 = (const float*)d_in[12]; const float* bk0 = (const float*)d_in[13];
    const float* Wv0 = (const float*)d_in[14]; const float* bv0 = (const float*)d_in[15];
    const float* Wo0 = (const float*)d_in[16]; const float* bo0 = (const float*)d_in[17];
    const float* Wq1 = (const float*)d_in[18]; const float* bq1 = (const float*)d_in[19];
    const float* Wk1 = (const float*)d_in[20]; const float* bk1 = (const float*)d_in[21];
    const float* Wv1 = (const float*)d_in[22]; const float* bv1 = (const float*)d_in[23];
    const float* Wo1 = (const float*)d_in[24]; const float* bo1 = (const float*)d_in[25];
    const float* g0  = (const float*)d_in[26];
    const float* g1  = (const float*)d_in[27];
    float* out = (float*)d_out;

    // branch 0 (s2t): q-norm=spec_q, kv-norm=spat_kv; branch 1 (t2s): q-norm=spat_q, kv-norm=spec_kv
    prep_all<<<1540, 256>>>(lsqg, ltkvg, ltqg, lskvg,
                            lsqb, ltkvb, ltqb, lskvb,
                            Wq0, bq0, Wk0, bk0, Wv0, bv0, Wo0,
                            Wq1, bq1, Wk1, bk1, Wv1, bv1, Wo1);

    cudaFuncSetAttribute(fusion_kernel, cudaFuncAttributeMaxDynamicSharedMemorySize, SMEM_BYTES);
    fusion_kernel<<<1024, 512, SMEM_BYTES>>>(xspec, xspat, bo0, bo1, g0, g1, out);
}

// round 7
// speedup vs baseline: 4.6991x; 1.5197x over previous
#include <cuda_runtime.h>
#include <cuda_fp16.h>
#include <cstdint>

#define OUT_HALF 16777216           // 8*64*128*256
#define LDH   264                   // half pitch for 128x256 half buffers
#define PP    264                   // weight panel pitch (halves)

#define BUF1_OFF 0                  // 67584 B : LN(x_kv) -> [K|V]
#define BUF2_OFF 67584              // 67584 B : LN(x_q) -> Q -> AO
#define PAN_OFF  135168             // 2 x 16896 B double-buffered weight panels
#define SMEM_BYTES 168960

// ---------------- folded weights (half) + biases (float) ---------------------------
__device__ __half g_Wq[2][65536];   // [k*256+n], gamma-q folded, * (1/sqrt(32))*log2(e)
__device__ __half g_Wkv[2][65536];  // [k*256+n], [K|V], gamma-kv folded
__device__ __half g_Wo[2][65536];   // [k*256+n]
__device__ float  g_bq[2][256];
__device__ float  g_bkv[2][256];

#define QS2 (0.17677669529663687f * 1.4426950408889634f)

// ---------------- PTX primitives ----------------------------------------------------
__device__ __forceinline__ uint32_t smem_u32(const void* p) {
    uint32_t a;
    asm("{ .reg .u64 t; cvta.to.shared.u64 t, %1; cvt.u32.u64 %0, t; }" : "=r"(a) : "l"(p));
    return a;
}
__device__ __forceinline__ void ldsm4(uint32_t* r, uint32_t a) {
    asm volatile("ldmatrix.sync.aligned.m8n8.x4.shared.b16 {%0,%1,%2,%3}, [%4];"
                 : "=r"(r[0]), "=r"(r[1]), "=r"(r[2]), "=r"(r[3]) : "r"(a));
}
__device__ __forceinline__ void ldsm4t(uint32_t* r, uint32_t a) {
    asm volatile("ldmatrix.sync.aligned.m8n8.x4.trans.shared.b16 {%0,%1,%2,%3}, [%4];"
                 : "=r"(r[0]), "=r"(r[1]), "=r"(r[2]), "=r"(r[3]) : "r"(a));
}
__device__ __forceinline__ void mma16816(float* c, const uint32_t* a, uint32_t b0, uint32_t b1) {
    asm volatile("mma.sync.aligned.m16n8k16.row.col.f32.f16.f16.f32 "
                 "{%0,%1,%2,%3}, {%4,%5,%6,%7}, {%8,%9}, {%0,%1,%2,%3};"
                 : "+f"(c[0]), "+f"(c[1]), "+f"(c[2]), "+f"(c[3])
                 : "r"(a[0]), "r"(a[1]), "r"(a[2]), "r"(a[3]), "r"(b0), "r"(b1));
}
__device__ __forceinline__ void cpa16(uint32_t dst, const void* src) {
    asm volatile("cp.async.ca.shared.global [%0], [%1], 16;" :: "r"(dst), "l"(src));
}
#define CP_COMMIT() asm volatile("cp.async.commit_group;")
#define CP_WAIT0()  asm volatile("cp.async.wait_group 0;")
__device__ __forceinline__ float ex2f(float x) {
    float y; asm("ex2.approx.f32 %0, %1;" : "=f"(y) : "f"(x)); return y;
}
__device__ __forceinline__ uint32_t h2u(float a, float b) {
    __half2 h = __floats2half2_rn(a, b);
    return *reinterpret_cast<uint32_t*>(&h);
}

// ---------------- single prep kernel ------------------------------------------------
__global__ void prep_all(const float* __restrict__ gq0, const float* __restrict__ gkv0,
                         const float* __restrict__ gq1, const float* __restrict__ gkv1,
                         const float* __restrict__ bqn0, const float* __restrict__ bkvn0,
                         const float* __restrict__ bqn1, const float* __restrict__ bkvn1,
                         const float* __restrict__ Wq0, const float* __restrict__ bq0,
                         const float* __restrict__ Wk0, const float* __restrict__ bk0,
                         const float* __restrict__ Wv0, const float* __restrict__ bv0,
                         const float* __restrict__ Wo0,
                         const float* __restrict__ Wq1, const float* __restrict__ bq1,
                         const float* __restrict__ Wk1, const float* __restrict__ bk1,
                         const float* __restrict__ Wv1, const float* __restrict__ bv1,
                         const float* __restrict__ Wo1) {
    int gid = blockIdx.x * blockDim.x + threadIdx.x;
    if (gid < 393216) {
        int br = gid / 196608, rem = gid - br * 196608;
        int mat = rem >> 16, e = rem & 65535;
        int k = e >> 8, n = e & 255;
        if (mat == 0) {
            const float* gq = br ? gq1 : gq0; const float* Wq = br ? Wq1 : Wq0;
            g_Wq[br][e] = __float2half_rn(gq[k] * Wq[e] * QS2);
        } else if (mat == 1) {
            const float* gkv = br ? gkv1 : gkv0;
            const float* Wk = br ? Wk1 : Wk0; const float* Wv = br ? Wv1 : Wv0;
            float w = (n < 128) ? Wk[k * 128 + n] : Wv[k * 128 + n - 128];
            g_Wkv[br][e] = __float2half_rn(gkv[k] * w);
        } else {
            const float* Wo = br ? Wo1 : Wo0;
            g_Wo[br][e] = __float2half_rn(Wo[e]);
        }
    } else if (gid < 394240) {
        int t = gid - 393216;
        int br = t >> 9, tt = t & 511;
        const float* bqn = br ? bqn1 : bqn0; const float* bkvn = br ? bkvn1 : bkvn0;
        const float* Wq = br ? Wq1 : Wq0; const float* Wk = br ? Wk1 : Wk0;
        const float* Wv = br ? Wv1 : Wv0;
        const float* bq = br ? bq1 : bq0; const float* bk = br ? bk1 : bk0;
        const float* bv = br ? bv1 : bv0;
        if (tt < 256) {
            float a = bq[tt];
            for (int k = 0; k < 256; ++k) a += bqn[k] * Wq[k * 256 + tt];
            g_bq[br][tt] = a * QS2;
        } else if (tt < 384) {
            int c = tt - 256; float a = bk[c];
            for (int k = 0; k < 256; ++k) a += bkvn[k] * Wk[k * 128 + c];
            g_bkv[br][c] = a;
        } else {
            int c = tt - 384; float a = bv[c];
            for (int k = 0; k < 256; ++k) a += bkvn[k] * Wv[k * 128 + c];
            g_bkv[br][c + 128] = a;
        }
    }
}

// ---------------- main fused kernel: 1 CTA = 2 sequences, 1 branch ------------------
__global__ void __launch_bounds__(512, 1)
fusion_kernel(const float* __restrict__ xspec, const float* __restrict__ xspat,
              const float* __restrict__ bo0, const float* __restrict__ bo1,
              const float* __restrict__ gate0, const float* __restrict__ gate1,
              float* __restrict__ out) {
    extern __shared__ char smc[];
    __half* buf1 = reinterpret_cast<__half*>(smc + BUF1_OFF);
    __half* buf2 = reinterpret_cast<__half*>(smc + BUF2_OFF);
    const uint32_t pan0 = smem_u32(smc + PAN_OFF);
    const uint32_t pan1 = pan0 + 16896;

    int tid = threadIdx.x, w = tid >> 5, lane = tid & 31;
    int br = blockIdx.x >> 9, pair = blockIdx.x & 511;

    const float* xq  = br ? xspat : xspec;
    const float* xkv = br ? xspec : xspat;
    const float* bo  = br ? bo1 : bo0;
    float gv = br ? gate1[0] : gate0[0];
    float sg = 1.0f / (1.0f + __expf(-gv));
    float* outb = out + (br ? OUT_HALF : 0);

    auto rbase = [&](int r) {
        int s = pair * 2 + (r >> 6);
        return ((s >> 7) * 8192 + (s & 127)) * 256 + (r & 63) * 32768;
    };

    // ---------- LN: 128 rows -> half buffer ----------
    auto ln_rows = [&](__half* dst, const float* __restrict__ src) {
        for (int r = w; r < 128; r += 16) {
            const float* rp = src + rbase(r);
            float4 u = *reinterpret_cast<const float4*>(rp + lane * 8);
            float4 v = *reinterpret_cast<const float4*>(rp + lane * 8 + 4);
            float s = u.x + u.y + u.z + u.w + v.x + v.y + v.z + v.w;
            float q = u.x * u.x + u.y * u.y + u.z * u.z + u.w * u.w +
                      v.x * v.x + v.y * v.y + v.z * v.z + v.w * v.w;
#pragma unroll
            for (int o = 16; o; o >>= 1) {
                s += __shfl_xor_sync(0xffffffffu, s, o);
                q += __shfl_xor_sync(0xffffffffu, q, o);
            }
            float mu = s * (1.0f / 256.0f);
            float rs = rsqrtf(q * (1.0f / 256.0f) - mu * mu + 1e-5f);
            uint4 pk;
            uint32_t* ph = reinterpret_cast<uint32_t*>(&pk);
            ph[0] = h2u((u.x - mu) * rs, (u.y - mu) * rs);
            ph[1] = h2u((u.z - mu) * rs, (u.w - mu) * rs);
            ph[2] = h2u((v.x - mu) * rs, (v.y - mu) * rs);
            ph[3] = h2u((v.z - mu) * rs, (v.w - mu) * rs);
            *reinterpret_cast<uint4*>(dst + r * LDH + lane * 8) = pk;
        }
    };

    // ---------- GEMM: C[128x256] = A @ W + bias (PTX mma, register epilogue) --------
    // MODE 0: C -> half into dsth (in-place over A allowed). MODE 1: residual to gmem.
    auto gemm128 = [&](const __half* Abuf, const __half* __restrict__ Wg,
                       const float* __restrict__ bias, __half* dsth, int MODE) {
        int m0 = (w & 3) * 32, n0 = (w >> 2) * 64;
        int l15 = lane & 15, lhi = (lane >> 4) * 8;
        uint32_t aBase = smem_u32(Abuf) + ((m0 + l15) * LDH + lhi) * 2;
        uint32_t bOff = (l15 * PP + n0 + lhi) * 2;

        float acc[16][4];
#pragma unroll
        for (int i = 0; i < 16; ++i)
#pragma unroll
            for (int j = 0; j < 4; ++j) acc[i][j] = 0.0f;

        auto stage = [&](int st, uint32_t pan) {
#pragma unroll
            for (int p = 0; p < 2; ++p) {
                int idx = tid + p * 512;
                int r = idx >> 5, cg = (idx & 31) * 8;
                cpa16(pan + (r * PP + cg) * 2, Wg + (st * 32 + r) * 256 + cg);
            }
            CP_COMMIT();
        };

        stage(0, pan0);
        for (int st = 0; st < 8; ++st) {
            CP_WAIT0();
            __syncthreads();
            if (st < 7) stage(st + 1, (st & 1) ? pan0 : pan1);
            uint32_t pan = (st & 1) ? pan1 : pan0;
#pragma unroll
            for (int kf = 0; kf < 2; ++kf) {
                uint32_t a0[4], a1[4];
                uint32_t ak = aBase + (st * 32 + kf * 16) * 2;
                ldsm4(a0, ak);
                ldsm4(a1, ak + 16 * LDH * 2);
#pragma unroll
                for (int ng = 0; ng < 4; ++ng) {
                    uint32_t bq4[4];
                    ldsm4t(bq4, pan + bOff + (kf * 16 * PP + ng * 16) * 2);
                    mma16816(acc[ng * 2],     a0, bq4[0], bq4[1]);
                    mma16816(acc[ng * 2 + 1], a0, bq4[2], bq4[3]);
                    mma16816(acc[8 + ng * 2],     a1, bq4[0], bq4[1]);
                    mma16816(acc[8 + ng * 2 + 1], a1, bq4[2], bq4[3]);
                }
            }
        }
        __syncthreads();   // all A reads complete before in-place epilogue writes

        int g = lane >> 2, c2 = (lane & 3) * 2;
        if (MODE == 0) {
#pragma unroll
            for (int nt = 0; nt < 8; ++nt) {
                int col = n0 + nt * 8 + c2;
                float2 bb = *reinterpret_cast<const float2*>(bias + col);
#pragma unroll
                for (int mi = 0; mi < 2; ++mi) {
                    float* a4 = acc[mi * 8 + nt];
                    uint32_t h0 = h2u(a4[0] + bb.x, a4[1] + bb.y);
                    uint32_t h1 = h2u(a4[2] + bb.x, a4[3] + bb.y);
                    *reinterpret_cast<uint32_t*>(dsth + (m0 + mi * 16 + g) * LDH + col) = h0;
                    *reinterpret_cast<uint32_t*>(dsth + (m0 + mi * 16 + 8 + g) * LDH + col) = h1;
                }
            }
        } else {
            int rb[4];
            rb[0] = rbase(m0 + g);      rb[1] = rbase(m0 + 8 + g);
            rb[2] = rbase(m0 + 16 + g); rb[3] = rbase(m0 + 24 + g);
#pragma unroll
            for (int nt = 0; nt < 8; ++nt) {
                int col = n0 + nt * 8 + c2;
                float2 bb = *reinterpret_cast<const float2*>(bias + col);
#pragma unroll
                for (int mi = 0; mi < 2; ++mi) {
                    float* a4 = acc[mi * 8 + nt];
#pragma unroll
                    for (int hrow = 0; hrow < 2; ++hrow) {
                        int off = rb[mi * 2 + hrow] + col;
                        float2 x = *reinterpret_cast<const float2*>(xq + off);
                        float2 o;
                        o.x = x.x + sg * (a4[hrow * 2 + 0] + bb.x);
                        o.y = x.y + sg * (a4[hrow * 2 + 1] + bb.y);
                        *reinterpret_cast<float2*>(outb + off) = o;
                    }
                }
            }
        }
        __syncthreads();
    };

    // ================= pipeline =================
    ln_rows(buf1, xkv);
    __syncthreads();
    gemm128(buf1, g_Wkv[br], g_bkv[br], buf1, 0);

    ln_rows(buf2, xq);
    __syncthreads();
    gemm128(buf2, g_Wq[br], g_bq[br], buf2, 0);

    // ================= attention: smem-free scores, P in regs, AO over Q_h ==========
    {
        int sm8 = w & 7;
        int seq = sm8 >> 2, mt = sm8 & 3;
        int rows0 = seq * 64 + mt * 16;
        int tok0 = seq * 64;
        int l15 = lane & 15, lhi = (lane >> 4) * 8;
        int g = lane >> 2, c2 = (lane & 3) * 2;
        uint32_t q_base = smem_u32(buf2) + ((rows0 + l15) * LDH + lhi) * 2;
        uint32_t k_base = smem_u32(buf1) + ((tok0 + l15) * LDH + lhi) * 2;

#pragma unroll
        for (int hh = 0; hh < 4; ++hh) {
            int h = (w >> 3) * 4 + hh;
            int qo = h * 32, ko = (h >> 1) * 32, vo = 128 + (h >> 1) * 32;
            // ---- QK: scores (16 rows x 64 keys) in registers ----
            uint32_t aQ[2][4];
            ldsm4(aQ[0], q_base + qo * 2);
            ldsm4(aQ[1], q_base + (qo + 16) * 2);
            float sc[8][4];
#pragma unroll
            for (int i = 0; i < 8; ++i)
#pragma unroll
                for (int j = 0; j < 4; ++j) sc[i][j] = 0.0f;
#pragma unroll
            for (int tb = 0; tb < 4; ++tb)
#pragma unroll
                for (int db = 0; db < 2; ++db) {
                    uint32_t kr[4];
                    ldsm4(kr, k_base + (tb * 16 * LDH + ko + db * 16) * 2);
                    mma16816(sc[2 * tb],     aQ[db], kr[0], kr[2]);
                    mma16816(sc[2 * tb + 1], aQ[db], kr[1], kr[3]);
                }
            // ---- register softmax (rows g and g+8 of this warp's 16) ----
            float mx0 = -3.4e38f, mx1 = -3.4e38f;
#pragma unroll
            for (int nt = 0; nt < 8; ++nt) {
                mx0 = fmaxf(mx0, fmaxf(sc[nt][0], sc[nt][1]));
                mx1 = fmaxf(mx1, fmaxf(sc[nt][2], sc[nt][3]));
            }
            mx0 = fmaxf(mx0, __shfl_xor_sync(0xffffffffu, mx0, 1));
            mx0 = fmaxf(mx0, __shfl_xor_sync(0xffffffffu, mx0, 2));
            mx1 = fmaxf(mx1, __shfl_xor_sync(0xffffffffu, mx1, 1));
            mx1 = fmaxf(mx1, __shfl_xor_sync(0xffffffffu, mx1, 2));
            float s0 = 0.0f, s1 = 0.0f;
#pragma unroll
            for (int nt = 0; nt < 8; ++nt) {
                sc[nt][0] = ex2f(sc[nt][0] - mx0); s0 += sc[nt][0];
                sc[nt][1] = ex2f(sc[nt][1] - mx0); s0 += sc[nt][1];
                sc[nt][2] = ex2f(sc[nt][2] - mx1); s1 += sc[nt][2];
                sc[nt][3] = ex2f(sc[nt][3] - mx1); s1 += sc[nt][3];
            }
            s0 += __shfl_xor_sync(0xffffffffu, s0, 1);
            s0 += __shfl_xor_sync(0xffffffffu, s0, 2);
            s1 += __shfl_xor_sync(0xffffffffu, s1, 1);
            s1 += __shfl_xor_sync(0xffffffffu, s1, 2);
            float i0 = 1.0f / s0, i1 = 1.0f / s1;
            // ---- P (half) as PV A-operand, directly from accumulators ----
            uint32_t aP[4][4];
#pragma unroll
            for (int kf = 0; kf < 4; ++kf) {
                float* p0 = sc[2 * kf];
                float* p1 = sc[2 * kf + 1];
                aP[kf][0] = h2u(p0[0] * i0, p0[1] * i0);
                aP[kf][1] = h2u(p0[2] * i1, p0[3] * i1);
                aP[kf][2] = h2u(p1[0] * i0, p1[1] * i0);
                aP[kf][3] = h2u(p1[2] * i1, p1[3] * i1);
            }
            // ---- PV: AO (16 rows x 32 dims) ----
            float ao[4][4];
#pragma unroll
            for (int i = 0; i < 4; ++i)
#pragma unroll
                for (int j = 0; j < 4; ++j) ao[i][j] = 0.0f;
#pragma unroll
            for (int kb = 0; kb < 4; ++kb)
#pragma unroll
                for (int db = 0; db < 2; ++db) {
                    uint32_t vr[4];
                    ldsm4t(vr, k_base + (kb * 16 * LDH + vo + db * 16) * 2);
                    mma16816(ao[2 * db],     aP[kb], vr[0], vr[1]);
                    mma16816(ao[2 * db + 1], aP[kb], vr[2], vr[3]);
                }
            // ---- AO -> half over Q_h (same warp's rows/cols: no barrier needed) ----
#pragma unroll
            for (int dn = 0; dn < 4; ++dn) {
                int col = qo + dn * 8 + c2;
                *reinterpret_cast<uint32_t*>(buf2 + (rows0 + g) * LDH + col) =
                    h2u(ao[dn][0], ao[dn][1]);
                *reinterpret_cast<uint32_t*>(buf2 + (rows0 + 8 + g) * LDH + col) =
                    h2u(ao[dn][2], ao[dn][3]);
            }
        }
    }
    __syncthreads();

    // ================= O projection + residual epilogue =================
    gemm128(buf2, g_Wo[br], bo, nullptr, 1);
}

// ---------------- host launcher -------------------------------------------------------
extern "C" void kernel_launch(void* const* d_in, const int* in_sizes, int n_in,
                              void* d_out, int out_size) {
    const float* xspec = (const float*)d_in[0];
    const float* xspat = (const float*)d_in[1];
    const float* lsqg  = (const float*)d_in[2];
    const float* lsqb  = (const float*)d_in[3];
    const float* lskvg = (const float*)d_in[4];
    const float* lskvb = (const float*)d_in[5];
    const float* ltqg  = (const float*)d_in[6];
    const float* ltqb  = (const float*)d_in[7];
    const float* ltkvg = (const float*)d_in[8];
    const float* ltkvb = (const float*)d_in[9];
    const float* Wq0 = (const float*)d_in[10]; const float* bq0 = (const float*)d_in[11];
    const float* Wk0 = (const float*)d_in[12]; const float* bk0 = (const float*)d_in[13];
    const float* Wv0 = (const float*)d_in[14]; const float* bv0 = (const float*)d_in[15];
    const float* Wo0 = (const float*)d_in[16]; const float* bo0 = (const float*)d_in[17];
    const float* Wq1 = (const float*)d_in[18]; const float* bq1 = (const float*)d_in[19];
    const float* Wk1 = (const float*)d_in[20]; const float* bk1 = (const float*)d_in[21];
    const float* Wv1 = (const float*)d_in[22]; const float* bv1 = (const float*)d_in[23];
    const float* Wo1 = (const float*)d_in[24]; const float* bo1 = (const float*)d_in[25];
    const float* g0  = (const float*)d_in[26];
    const float* g1  = (const float*)d_in[27];
    float* out = (float*)d_out;

    // branch 0 (s2t): q-norm=spec_q, kv-norm=spat_kv; branch 1 (t2s): q-norm=spat_q, kv-norm=spec_kv
    prep_all<<<1540, 256>>>(lsqg, ltkvg, ltqg, lskvg,
                            lsqb, ltkvb, ltqb, lskvb,
                            Wq0, bq0, Wk0, bk0, Wv0, bv0, Wo0,
                            Wq1, bq1, Wk1, bk1, Wv1, bv1, Wo1);

    cudaFuncSetAttribute(fusion_kernel, cudaFuncAttributeMaxDynamicSharedMemorySize, SMEM_BYTES);
    fusion_kernel<<<1024, 512, SMEM_BYTES>>>(xspec, xspat, bo0, bo1, g0, g1, out);
}